// round 3
// baseline (speedup 1.0000x reference)
#include <cuda_runtime.h>
#include <cuda_fp16.h>
#include <cstdint>

#define NB 4
#define NC 256
#define NHW 4096
#define NG 32
#define CPG (NC/NG)

// ---------------- scratch (static device globals; no allocation) -------------
__device__ float  g_h [(size_t)NB*NHW*NC];   // groupnorm out, [b][n][c]
__device__ __half g_q [(size_t)NB*NHW*NC];   // centered quant q, [b][n][c]
__device__ __half g_k [(size_t)NB*NHW*NC];   // centered quant k, [b][m][c]
__device__ __half g_v [(size_t)NB*NC*NHW];   // centered quant v, [b][c][m]
__device__ float  g_S [(size_t)NB*NHW*NHW];  // attn logits,     [b][n][m]
__device__ __half g_W [(size_t)NB*NHW*NHW];  // quant probs,     [b][n][m]
__device__ float  g_ho[(size_t)NB*NHW*NC];   // attn out,        [b][n][c]

// ---------------- helpers ----------------------------------------------------
__device__ __forceinline__ void cp16(void* sm, const void* gm){
    unsigned sa = (unsigned)__cvta_generic_to_shared(sm);
    asm volatile("cp.async.cg.shared.global [%0], [%1], 16;\n" :: "r"(sa), "l"(gm));
}
__device__ __forceinline__ void cp_commit(){ asm volatile("cp.async.commit_group;\n"); }
template<int N> __device__ __forceinline__ void cp_wait(){
    asm volatile("cp.async.wait_group %0;\n" :: "n"(N));
}
__device__ __forceinline__ void mma16816(float* c, const unsigned* a, const unsigned* b){
    asm volatile(
        "mma.sync.aligned.m16n8k16.row.col.f32.f16.f16.f32 "
        "{%0,%1,%2,%3}, {%4,%5,%6,%7}, {%8,%9}, {%0,%1,%2,%3};\n"
        : "+f"(c[0]), "+f"(c[1]), "+f"(c[2]), "+f"(c[3])
        : "r"(a[0]), "r"(a[1]), "r"(a[2]), "r"(a[3]), "r"(b[0]), "r"(b[1]));
}

// ---------------- 1. GroupNorm ----------------------------------------------
__global__ __launch_bounds__(256) void gn_kernel(const float* __restrict__ x,
                                                 const float* __restrict__ sc,
                                                 const float* __restrict__ bi){
    int b = blockIdx.x / NG, g = blockIdx.x % NG;
    const float* xp = x + ((size_t)b*NC + (size_t)g*CPG)*NHW;
    const int NE = CPG*NHW;
    float s = 0.f, s2 = 0.f;
    for (int i = threadIdx.x; i < NE; i += 256){ float v = xp[i]; s += v; s2 += v*v; }
    __shared__ float r1[256], r2[256];
    r1[threadIdx.x] = s; r2[threadIdx.x] = s2; __syncthreads();
    for (int o = 128; o > 0; o >>= 1){
        if (threadIdx.x < o){ r1[threadIdx.x] += r1[threadIdx.x+o]; r2[threadIdx.x] += r2[threadIdx.x+o]; }
        __syncthreads();
    }
    float mean = r1[0] / NE;
    float var  = r2[0] / NE - mean*mean;
    float rstd = rsqrtf(var + 1e-6f);
    for (int i = threadIdx.x; i < NE; i += 256){
        int c = g*CPG + i/NHW; int n = i % NHW;
        g_h[((size_t)b*NHW + n)*NC + c] = (xp[i] - mean)*rstd*sc[c] + bi[c];
    }
}

// ---------------- 2. QKV fp32 SGEMM-NT + quantize ---------------------------
__global__ __launch_bounds__(256) void qkv_kernel(
    const float* __restrict__ wq, const float* __restrict__ bq,
    const float* __restrict__ wk, const float* __restrict__ bk,
    const float* __restrict__ wv, const float* __restrict__ bv,
    const float* pdq, const float* pzq, const float* pdk, const float* pzk,
    const float* pdv, const float* pzv)
{
    int b = blockIdx.z / 3, which = blockIdx.z % 3;
    const float *Wt, *bias, *pd, *pz; __half* out;
    if (which == 0){ Wt = wq; bias = bq; pd = pdq; pz = pzq; out = g_q; }
    else if (which == 1){ Wt = wk; bias = bk; pd = pdk; pz = pzk; out = g_k; }
    else { Wt = wv; bias = bv; pd = pdv; pz = pzv; out = g_v; }
    const float* Ab = g_h + (size_t)b*NHW*NC;
    int n0 = blockIdx.x*64, o0 = blockIdx.y*64;
    __shared__ float As[64][17], Bs[64][17];
    float acc[4][4] = {};
    int tx = threadIdx.x & 15, ty = threadIdx.x >> 4;
    int lr = threadIdx.x >> 2, ls = threadIdx.x & 3;
    for (int k0 = 0; k0 < NC; k0 += 16){
        float4 va = *(const float4*)(Ab + (size_t)(n0+lr)*NC + k0 + ls*4);
        float4 vb = *(const float4*)(Wt + (size_t)(o0+lr)*NC + k0 + ls*4);
        As[lr][ls*4+0]=va.x; As[lr][ls*4+1]=va.y; As[lr][ls*4+2]=va.z; As[lr][ls*4+3]=va.w;
        Bs[lr][ls*4+0]=vb.x; Bs[lr][ls*4+1]=vb.y; Bs[lr][ls*4+2]=vb.z; Bs[lr][ls*4+3]=vb.w;
        __syncthreads();
        #pragma unroll
        for (int kk = 0; kk < 16; kk++){
            float a[4], bb[4];
            #pragma unroll
            for (int r = 0; r < 4; r++) a[r]  = As[ty*4+r][kk];
            #pragma unroll
            for (int c = 0; c < 4; c++) bb[c] = Bs[tx*4+c][kk];
            #pragma unroll
            for (int r = 0; r < 4; r++)
                #pragma unroll
                for (int c = 0; c < 4; c++) acc[r][c] += a[r]*bb[c];
        }
        __syncthreads();
    }
    float delta = pd[0], zp = pz[0];
    float inv = 1.f/delta, lo = -zp, hi = 255.f - zp;
    #pragma unroll
    for (int r = 0; r < 4; r++)
        #pragma unroll
        for (int c = 0; c < 4; c++){
            int n = n0 + ty*4 + r, o = o0 + tx*4 + c;
            float qv = acc[r][c] + bias[o];
            float iq = fminf(fmaxf(rintf(qv*inv), lo), hi);
            __half hv = __float2half_rn(iq);
            if (which < 2) out[((size_t)b*NHW + n)*NC + o] = hv;
            else           out[((size_t)b*NC  + o)*NHW + n] = hv;
        }
}

// ---------------- 3/5. generic HMMA NT GEMM (fp16 in, fp32 out) -------------
// C[i,j] = scale * sum_k A[i,k]*B[j,k];  A:[M][lda], B:[N][ldb], C:[M][ldc]
// batch = blockIdx.z with strides M*lda / N*ldb / M*ldc.
__global__ __launch_bounds__(256) void mma_nt(
    const __half* __restrict__ Ag, const __half* __restrict__ Bg, float* __restrict__ Cg,
    int M, int N, int K, int lda, int ldb, int ldc,
    const float* sa, const float* sb, float smul)
{
    __shared__ __align__(16) __half As[2][128][40];
    __shared__ __align__(16) __half Bs[2][128][40];
    int bz = blockIdx.z;
    const __half* A  = Ag + (size_t)bz*M*lda;
    const __half* Bp = Bg + (size_t)bz*N*ldb;
    float*        Cp = Cg + (size_t)bz*M*ldc;
    int m0 = blockIdx.x*128, n0 = blockIdx.y*128;
    int tid = threadIdx.x, lane = tid & 31, warp = tid >> 5;
    int wm = warp >> 1, wn = warp & 1;          // 4 x 2 warp grid, 32x64 per warp
    int r = lane >> 2, cq = (lane & 3)*2;
    float acc[2][8][4];
    #pragma unroll
    for (int i = 0; i < 2; i++)
        #pragma unroll
        for (int j = 0; j < 8; j++)
            #pragma unroll
            for (int t = 0; t < 4; t++) acc[i][j][t] = 0.f;

    int KT = K/32;
    auto prefetch = [&](int kt, int buf){
        int k0 = kt*32;
        #pragma unroll
        for (int it = 0; it < 2; ++it){
            int flat = tid + it*256;
            int row = flat >> 2, seg = flat & 3;
            cp16(&As[buf][row][seg*8], A  + (size_t)(m0+row)*lda + k0 + seg*8);
            cp16(&Bs[buf][row][seg*8], Bp + (size_t)(n0+row)*ldb + k0 + seg*8);
        }
        cp_commit();
    };

    prefetch(0, 0);
    for (int kt = 0; kt < KT; ++kt){
        int cur = kt & 1;
        if (kt + 1 < KT){ prefetch(kt+1, cur^1); cp_wait<1>(); }
        else            cp_wait<0>();
        __syncthreads();
        #pragma unroll
        for (int kk = 0; kk < 32; kk += 16){
            unsigned af[2][4], bf[8][2];
            #pragma unroll
            for (int i = 0; i < 2; i++){
                int mr = wm*32 + i*16;
                af[i][0] = *(const unsigned*)&As[cur][mr + r    ][kk + cq    ];
                af[i][1] = *(const unsigned*)&As[cur][mr + r + 8][kk + cq    ];
                af[i][2] = *(const unsigned*)&As[cur][mr + r    ][kk + cq + 8];
                af[i][3] = *(const unsigned*)&As[cur][mr + r + 8][kk + cq + 8];
            }
            #pragma unroll
            for (int j = 0; j < 8; j++){
                int nr = wn*64 + j*8 + r;
                bf[j][0] = *(const unsigned*)&Bs[cur][nr][kk + cq    ];
                bf[j][1] = *(const unsigned*)&Bs[cur][nr][kk + cq + 8];
            }
            #pragma unroll
            for (int i = 0; i < 2; i++)
                #pragma unroll
                for (int j = 0; j < 8; j++) mma16816(acc[i][j], af[i], bf[j]);
        }
        __syncthreads();
    }
    float scale = sa[0]*sb[0]*smul;
    #pragma unroll
    for (int i = 0; i < 2; i++)
        #pragma unroll
        for (int j = 0; j < 8; j++){
            int row = m0 + wm*32 + i*16 + r;
            int col = n0 + wn*64 + j*8 + cq;
            float2 v0 = make_float2(acc[i][j][0]*scale, acc[i][j][1]*scale);
            float2 v1 = make_float2(acc[i][j][2]*scale, acc[i][j][3]*scale);
            *(float2*)(Cp + (size_t)row*ldc + col)     = v0;
            *(float2*)(Cp + (size_t)(row+8)*ldc + col) = v1;
        }
}

// ---------------- 4. softmax + prob quantization -----------------------------
__global__ __launch_bounds__(256) void softmax_kernel(const float* pdw, const float* pzw){
    size_t rowi = blockIdx.x;                  // b*NHW + n
    const float* S = g_S + rowi*NHW;
    __half*      Wp = g_W + rowi*NHW;
    __shared__ float sh[NHW];
    __shared__ float red[256];
    int tid = threadIdx.x;
    float mx = -1e30f;
    for (int i = tid; i < NHW; i += 256){ float v = S[i]; sh[i] = v; mx = fmaxf(mx, v); }
    red[tid] = mx; __syncthreads();
    for (int o = 128; o > 0; o >>= 1){ if (tid < o) red[tid] = fmaxf(red[tid], red[tid+o]); __syncthreads(); }
    mx = red[0]; __syncthreads();
    float sum = 0.f;
    for (int i = tid; i < NHW; i += 256){ float e = expf(sh[i]-mx); sh[i] = e; sum += e; }
    red[tid] = sum; __syncthreads();
    for (int o = 128; o > 0; o >>= 1){ if (tid < o) red[tid] += red[tid+o]; __syncthreads(); }
    float total = red[0];
    float dwv = pdw[0], zwv = pzw[0];
    float inv = 1.f/(total*dwv);
    float lo = -zwv, hi = 255.f - zwv;
    for (int i = tid; i < NHW; i += 256){
        float wv = fminf(fmaxf(rintf(sh[i]*inv), lo), hi);
        Wp[i] = __float2half_rn(wv);
    }
}

// ---------------- 6. proj + bias + residual ----------------------------------
__global__ __launch_bounds__(256) void proj_kernel(
    const float* __restrict__ wp, const float* __restrict__ bp,
    const float* __restrict__ x, float* __restrict__ out)
{
    int b = blockIdx.z;
    const float* Bb = g_ho + (size_t)b*NHW*NC;
    int n0 = blockIdx.x*64, o0 = blockIdx.y*64;
    __shared__ float As[64][17], Bs[64][17];
    float acc[4][4] = {};
    int tx = threadIdx.x & 15, ty = threadIdx.x >> 4;
    int lr = threadIdx.x >> 2, ls = threadIdx.x & 3;
    for (int k0 = 0; k0 < NC; k0 += 16){
        float4 va = *(const float4*)(wp + (size_t)(o0+lr)*NC + k0 + ls*4);
        float4 vb = *(const float4*)(Bb + (size_t)(n0+lr)*NC + k0 + ls*4);
        As[lr][ls*4+0]=va.x; As[lr][ls*4+1]=va.y; As[lr][ls*4+2]=va.z; As[lr][ls*4+3]=va.w;
        Bs[lr][ls*4+0]=vb.x; Bs[lr][ls*4+1]=vb.y; Bs[lr][ls*4+2]=vb.z; Bs[lr][ls*4+3]=vb.w;
        __syncthreads();
        #pragma unroll
        for (int kk = 0; kk < 16; kk++){
            float a[4], bb[4];
            #pragma unroll
            for (int r = 0; r < 4; r++) a[r]  = As[ty*4+r][kk];
            #pragma unroll
            for (int c = 0; c < 4; c++) bb[c] = Bs[tx*4+c][kk];
            #pragma unroll
            for (int r = 0; r < 4; r++)
                #pragma unroll
                for (int c = 0; c < 4; c++) acc[r][c] += a[r]*bb[c];
        }
        __syncthreads();
    }
    #pragma unroll
    for (int r = 0; r < 4; r++)
        #pragma unroll
        for (int c = 0; c < 4; c++){
            int o = o0 + ty*4 + r, n = n0 + tx*4 + c;
            size_t idx = ((size_t)b*NC + o)*NHW + n;
            out[idx] = x[idx] + bp[o] + acc[r][c];
        }
}

// ---------------- launch ------------------------------------------------------
extern "C" void kernel_launch(void* const* d_in, const int* in_sizes, int n_in,
                              void* d_out, int out_size){
    const float* x   = (const float*)d_in[0];
    const float* gsc = (const float*)d_in[1];
    const float* gbi = (const float*)d_in[2];
    const float* wq  = (const float*)d_in[3];  const float* bq = (const float*)d_in[4];
    const float* wk  = (const float*)d_in[5];  const float* bk = (const float*)d_in[6];
    const float* wv  = (const float*)d_in[7];  const float* bv = (const float*)d_in[8];
    const float* wp  = (const float*)d_in[9];  const float* bp = (const float*)d_in[10];
    const float* dq  = (const float*)d_in[11]; const float* zq = (const float*)d_in[12];
    const float* dk  = (const float*)d_in[13]; const float* zk = (const float*)d_in[14];
    const float* dv  = (const float*)d_in[15]; const float* zv = (const float*)d_in[16];
    const float* dw  = (const float*)d_in[17]; const float* zw = (const float*)d_in[18];
    float* out = (float*)d_out;

    void *pq, *pk, *pv, *pS, *pW, *pho;
    cudaGetSymbolAddress(&pq,  g_q);
    cudaGetSymbolAddress(&pk,  g_k);
    cudaGetSymbolAddress(&pv,  g_v);
    cudaGetSymbolAddress(&pS,  g_S);
    cudaGetSymbolAddress(&pW,  g_W);
    cudaGetSymbolAddress(&pho, g_ho);

    gn_kernel<<<NB*NG, 256>>>(x, gsc, gbi);
    qkv_kernel<<<dim3(NHW/64, NC/64, NB*3), 256>>>(wq, bq, wk, bk, wv, bv,
                                                   dq, zq, dk, zk, dv, zv);
    // S = q . k^T * (dq*dk/16)
    mma_nt<<<dim3(NHW/128, NHW/128, NB), 256>>>(
        (const __half*)pq, (const __half*)pk, (float*)pS,
        NHW, NHW, NC, NC, NC, NHW, dq, dk, 0.0625f);
    softmax_kernel<<<NB*NHW, 256>>>(dw, zw);
    // h_out[n][c] = W . v^T * (dv*dw)
    mma_nt<<<dim3(NHW/128, NC/128, NB), 256>>>(
        (const __half*)pW, (const __half*)pv, (float*)pho,
        NHW, NC, NHW, NHW, NHW, NC, dv, dw, 1.0f);
    proj_kernel<<<dim3(NHW/64, NC/64, NB), 256>>>(wp, bp, x, out);
}

// round 6
// speedup vs baseline: 1.1956x; 1.1956x over previous
#include <cuda_runtime.h>
#include <cuda_fp16.h>
#include <cstdint>

#define NB 4
#define NC 256
#define NHW 4096
#define NG 32
#define CPG (NC/NG)

// ---------------- scratch (static device globals; no allocation) -------------
__device__ float  g_h [(size_t)NB*NHW*NC];   // groupnorm out, [b][n][c]
__device__ __half g_q [(size_t)NB*NHW*NC];   // centered quant q, [b][n][c]
__device__ __half g_k [(size_t)NB*NHW*NC];   // centered quant k, [b][m][c]
__device__ __half g_v [(size_t)NB*NC*NHW];   // centered quant v, [b][c][m]
__device__ float  g_S [(size_t)NB*NHW*NHW];  // attn logits,     [b][n][m]
__device__ __half g_W [(size_t)NB*NHW*NHW];  // quant probs,     [b][n][m]
__device__ float  g_ho[(size_t)NB*NHW*NC];   // attn out,        [b][n][c]

// ---------------- helpers ----------------------------------------------------
__device__ __forceinline__ void cp16(void* sm, const void* gm){
    unsigned sa = (unsigned)__cvta_generic_to_shared(sm);
    asm volatile("cp.async.cg.shared.global [%0], [%1], 16;\n" :: "r"(sa), "l"(gm));
}
__device__ __forceinline__ void cp_commit(){ asm volatile("cp.async.commit_group;\n"); }
template<int N> __device__ __forceinline__ void cp_wait(){
    asm volatile("cp.async.wait_group %0;\n" :: "n"(N));
}
__device__ __forceinline__ void mma16816(float* c, const unsigned* a, const unsigned* b){
    asm volatile(
        "mma.sync.aligned.m16n8k16.row.col.f32.f16.f16.f32 "
        "{%0,%1,%2,%3}, {%4,%5,%6,%7}, {%8,%9}, {%0,%1,%2,%3};\n"
        : "+f"(c[0]), "+f"(c[1]), "+f"(c[2]), "+f"(c[3])
        : "r"(a[0]), "r"(a[1]), "r"(a[2]), "r"(a[3]), "r"(b[0]), "r"(b[1]));
}

// ---------------- 1. GroupNorm (coalesced float4 stores) ---------------------
__global__ __launch_bounds__(256) void gn_kernel(const float* __restrict__ x,
                                                 const float* __restrict__ sc,
                                                 const float* __restrict__ bi){
    int b = blockIdx.x / NG, g = blockIdx.x % NG;
    const float* xp = x + ((size_t)b*NC + (size_t)g*CPG)*NHW;
    const int NE = CPG*NHW;
    float s = 0.f, s2 = 0.f;
    for (int i = threadIdx.x; i < NE; i += 256){ float v = xp[i]; s += v; s2 += v*v; }
    __shared__ float r1[256], r2[256];
    r1[threadIdx.x] = s; r2[threadIdx.x] = s2; __syncthreads();
    for (int o = 128; o > 0; o >>= 1){
        if (threadIdx.x < o){ r1[threadIdx.x] += r1[threadIdx.x+o]; r2[threadIdx.x] += r2[threadIdx.x+o]; }
        __syncthreads();
    }
    float mean = r1[0] / NE;
    float var  = r2[0] / NE - mean*mean;
    float rstd = rsqrtf(var + 1e-6f);
    float scv[CPG], biv[CPG];
    #pragma unroll
    for (int c = 0; c < CPG; c++){ scv[c] = sc[g*CPG + c]*rstd; biv[c] = bi[g*CPG + c]; }
    // phase 2: one thread per n -> write all CPG channels as two float4 (32B coalesced)
    for (int n = threadIdx.x; n < NHW; n += 256){
        float vals[CPG];
        #pragma unroll
        for (int c = 0; c < CPG; c++)
            vals[c] = (xp[(size_t)c*NHW + n] - mean)*scv[c] + biv[c];
        float4* dst = (float4*)&g_h[((size_t)b*NHW + n)*NC + g*CPG];
        dst[0] = make_float4(vals[0], vals[1], vals[2], vals[3]);
        dst[1] = make_float4(vals[4], vals[5], vals[6], vals[7]);
    }
}

// ---------------- 2. QKV fp32 SGEMM-NT + quantize ---------------------------
__global__ __launch_bounds__(256) void qkv_kernel(
    const float* __restrict__ wq, const float* __restrict__ bq,
    const float* __restrict__ wk, const float* __restrict__ bk,
    const float* __restrict__ wv, const float* __restrict__ bv,
    const float* pdq, const float* pzq, const float* pdk, const float* pzk,
    const float* pdv, const float* pzv)
{
    int b = blockIdx.z / 3, which = blockIdx.z % 3;
    const float *Wt, *bias, *pd, *pz; __half* out;
    if (which == 0){ Wt = wq; bias = bq; pd = pdq; pz = pzq; out = g_q; }
    else if (which == 1){ Wt = wk; bias = bk; pd = pdk; pz = pzk; out = g_k; }
    else { Wt = wv; bias = bv; pd = pdv; pz = pzv; out = g_v; }
    const float* Ab = g_h + (size_t)b*NHW*NC;
    int n0 = blockIdx.x*64, o0 = blockIdx.y*64;
    __shared__ float As[64][17], Bs[64][17];
    float acc[4][4] = {};
    int tx = threadIdx.x & 15, ty = threadIdx.x >> 4;
    int lr = threadIdx.x >> 2, ls = threadIdx.x & 3;
    for (int k0 = 0; k0 < NC; k0 += 16){
        float4 va = *(const float4*)(Ab + (size_t)(n0+lr)*NC + k0 + ls*4);
        float4 vb = *(const float4*)(Wt + (size_t)(o0+lr)*NC + k0 + ls*4);
        As[lr][ls*4+0]=va.x; As[lr][ls*4+1]=va.y; As[lr][ls*4+2]=va.z; As[lr][ls*4+3]=va.w;
        Bs[lr][ls*4+0]=vb.x; Bs[lr][ls*4+1]=vb.y; Bs[lr][ls*4+2]=vb.z; Bs[lr][ls*4+3]=vb.w;
        __syncthreads();
        #pragma unroll
        for (int kk = 0; kk < 16; kk++){
            float a[4], bb[4];
            #pragma unroll
            for (int r = 0; r < 4; r++) a[r]  = As[ty*4+r][kk];
            #pragma unroll
            for (int c = 0; c < 4; c++) bb[c] = Bs[tx*4+c][kk];
            #pragma unroll
            for (int r = 0; r < 4; r++)
                #pragma unroll
                for (int c = 0; c < 4; c++) acc[r][c] += a[r]*bb[c];
        }
        __syncthreads();
    }
    float delta = pd[0], zp = pz[0];
    float inv = 1.f/delta, lo = -zp, hi = 255.f - zp;
    #pragma unroll
    for (int r = 0; r < 4; r++)
        #pragma unroll
        for (int c = 0; c < 4; c++){
            int n = n0 + ty*4 + r, o = o0 + tx*4 + c;
            float qv = acc[r][c] + bias[o];
            float iq = fminf(fmaxf(rintf(qv*inv), lo), hi);
            __half hv = __float2half_rn(iq);
            if (which < 2) out[((size_t)b*NHW + n)*NC + o] = hv;
            else           out[((size_t)b*NC  + o)*NHW + n] = hv;
        }
}

// ---------------- 3/5. generic HMMA NT GEMM (fp16 in, fp32 out) -------------
__global__ __launch_bounds__(256) void mma_nt(
    const __half* __restrict__ Ag, const __half* __restrict__ Bg, float* __restrict__ Cg,
    int M, int N, int K, int lda, int ldb, int ldc,
    const float* sa, const float* sb, float smul)
{
    __shared__ __align__(16) __half As[2][128][40];
    __shared__ __align__(16) __half Bs[2][128][40];
    int bz = blockIdx.z;
    const __half* A  = Ag + (size_t)bz*M*lda;
    const __half* Bp = Bg + (size_t)bz*N*ldb;
    float*        Cp = Cg + (size_t)bz*M*ldc;
    int m0 = blockIdx.x*128, n0 = blockIdx.y*128;
    int tid = threadIdx.x, lane = tid & 31, warp = tid >> 5;
    int wm = warp >> 1, wn = warp & 1;          // 4 x 2 warp grid, 32x64 per warp
    int r = lane >> 2, cq = (lane & 3)*2;
    float acc[2][8][4];
    #pragma unroll
    for (int i = 0; i < 2; i++)
        #pragma unroll
        for (int j = 0; j < 8; j++)
            #pragma unroll
            for (int t = 0; t < 4; t++) acc[i][j][t] = 0.f;

    int KT = K/32;
    auto prefetch = [&](int kt, int buf){
        int k0 = kt*32;
        #pragma unroll
        for (int it = 0; it < 2; ++it){
            int flat = tid + it*256;
            int row = flat >> 2, seg = flat & 3;
            cp16(&As[buf][row][seg*8], A  + (size_t)(m0+row)*lda + k0 + seg*8);
            cp16(&Bs[buf][row][seg*8], Bp + (size_t)(n0+row)*ldb + k0 + seg*8);
        }
        cp_commit();
    };

    prefetch(0, 0);
    for (int kt = 0; kt < KT; ++kt){
        int cur = kt & 1;
        if (kt + 1 < KT){ prefetch(kt+1, cur^1); cp_wait<1>(); }
        else            cp_wait<0>();
        __syncthreads();
        #pragma unroll
        for (int kk = 0; kk < 32; kk += 16){
            unsigned af[2][4], bf[8][2];
            #pragma unroll
            for (int i = 0; i < 2; i++){
                int mr = wm*32 + i*16;
                af[i][0] = *(const unsigned*)&As[cur][mr + r    ][kk + cq    ];
                af[i][1] = *(const unsigned*)&As[cur][mr + r + 8][kk + cq    ];
                af[i][2] = *(const unsigned*)&As[cur][mr + r    ][kk + cq + 8];
                af[i][3] = *(const unsigned*)&As[cur][mr + r + 8][kk + cq + 8];
            }
            #pragma unroll
            for (int j = 0; j < 8; j++){
                int nr = wn*64 + j*8 + r;
                bf[j][0] = *(const unsigned*)&Bs[cur][nr][kk + cq    ];
                bf[j][1] = *(const unsigned*)&Bs[cur][nr][kk + cq + 8];
            }
            #pragma unroll
            for (int i = 0; i < 2; i++)
                #pragma unroll
                for (int j = 0; j < 8; j++) mma16816(acc[i][j], af[i], bf[j]);
        }
        __syncthreads();
    }
    float scale = sa[0]*sb[0]*smul;
    #pragma unroll
    for (int i = 0; i < 2; i++)
        #pragma unroll
        for (int j = 0; j < 8; j++){
            int row = m0 + wm*32 + i*16 + r;
            int col = n0 + wn*64 + j*8 + cq;
            float2 v0 = make_float2(acc[i][j][0]*scale, acc[i][j][1]*scale);
            float2 v1 = make_float2(acc[i][j][2]*scale, acc[i][j][3]*scale);
            *(float2*)(Cp + (size_t)row*ldc + col)     = v0;
            *(float2*)(Cp + (size_t)(row+8)*ldc + col) = v1;
        }
}

// ---------------- 4. softmax + prob quantization (register-resident) ---------
__global__ __launch_bounds__(256) void softmax_kernel(const float* pdw, const float* pzw){
    size_t rowi = blockIdx.x;                  // b*NHW + n
    const float4* S4 = (const float4*)(g_S + rowi*NHW);
    __half*       Wp = g_W + rowi*NHW;
    int tid = threadIdx.x, lane = tid & 31, wid = tid >> 5;
    __shared__ float redm[8], reds[8];

    float4 v[4];
    #pragma unroll
    for (int i = 0; i < 4; i++) v[i] = S4[tid + 256*i];

    // ---- block max ----
    float mx = -1e30f;
    #pragma unroll
    for (int i = 0; i < 4; i++){
        mx = fmaxf(mx, fmaxf(fmaxf(v[i].x, v[i].y), fmaxf(v[i].z, v[i].w)));
    }
    #pragma unroll
    for (int o = 16; o > 0; o >>= 1) mx = fmaxf(mx, __shfl_xor_sync(0xffffffffu, mx, o));
    if (lane == 0) redm[wid] = mx;
    __syncthreads();
    mx = redm[0];
    #pragma unroll
    for (int w = 1; w < 8; w++) mx = fmaxf(mx, redm[w]);

    // ---- exp + block sum ----
    float sum = 0.f;
    #pragma unroll
    for (int i = 0; i < 4; i++){
        v[i].x = __expf(v[i].x - mx); sum += v[i].x;
        v[i].y = __expf(v[i].y - mx); sum += v[i].y;
        v[i].z = __expf(v[i].z - mx); sum += v[i].z;
        v[i].w = __expf(v[i].w - mx); sum += v[i].w;
    }
    #pragma unroll
    for (int o = 16; o > 0; o >>= 1) sum += __shfl_xor_sync(0xffffffffu, sum, o);
    if (lane == 0) reds[wid] = sum;
    __syncthreads();
    float total = reds[0];
    #pragma unroll
    for (int w = 1; w < 8; w++) total += reds[w];

    // ---- quantize + packed store ----
    float dwv = pdw[0], zwv = pzw[0];
    float inv = 1.f/(total*dwv);
    float lo = -zwv, hi = 255.f - zwv;
    #pragma unroll
    for (int i = 0; i < 4; i++){
        __half h0 = __float2half_rn(fminf(fmaxf(rintf(v[i].x*inv), lo), hi));
        __half h1 = __float2half_rn(fminf(fmaxf(rintf(v[i].y*inv), lo), hi));
        __half h2 = __float2half_rn(fminf(fmaxf(rintf(v[i].z*inv), lo), hi));
        __half h3 = __float2half_rn(fminf(fmaxf(rintf(v[i].w*inv), lo), hi));
        __half2 p0 = __halves2half2(h0, h1);
        __half2 p1 = __halves2half2(h2, h3);
        uint2 pk;
        pk.x = *(unsigned*)&p0;
        pk.y = *(unsigned*)&p1;
        *(uint2*)(Wp + 4*tid + 1024*i) = pk;
    }
}

// ---------------- 6. proj + bias + residual ----------------------------------
__global__ __launch_bounds__(256) void proj_kernel(
    const float* __restrict__ wp, const float* __restrict__ bp,
    const float* __restrict__ x, float* __restrict__ out)
{
    int b = blockIdx.z;
    const float* Bb = g_ho + (size_t)b*NHW*NC;
    int n0 = blockIdx.x*64, o0 = blockIdx.y*64;
    __shared__ float As[64][17], Bs[64][17];
    float acc[4][4] = {};
    int tx = threadIdx.x & 15, ty = threadIdx.x >> 4;
    int lr = threadIdx.x >> 2, ls = threadIdx.x & 3;
    for (int k0 = 0; k0 < NC; k0 += 16){
        float4 va = *(const float4*)(wp + (size_t)(o0+lr)*NC + k0 + ls*4);
        float4 vb = *(const float4*)(Bb + (size_t)(n0+lr)*NC + k0 + ls*4);
        As[lr][ls*4+0]=va.x; As[lr][ls*4+1]=va.y; As[lr][ls*4+2]=va.z; As[lr][ls*4+3]=va.w;
        Bs[lr][ls*4+0]=vb.x; Bs[lr][ls*4+1]=vb.y; Bs[lr][ls*4+2]=vb.z; Bs[lr][ls*4+3]=vb.w;
        __syncthreads();
        #pragma unroll
        for (int kk = 0; kk < 16; kk++){
            float a[4], bb[4];
            #pragma unroll
            for (int r = 0; r < 4; r++) a[r]  = As[ty*4+r][kk];
            #pragma unroll
            for (int c = 0; c < 4; c++) bb[c] = Bs[tx*4+c][kk];
            #pragma unroll
            for (int r = 0; r < 4; r++)
                #pragma unroll
                for (int c = 0; c < 4; c++) acc[r][c] += a[r]*bb[c];
        }
        __syncthreads();
    }
    #pragma unroll
    for (int r = 0; r < 4; r++)
        #pragma unroll
        for (int c = 0; c < 4; c++){
            int o = o0 + ty*4 + r, n = n0 + tx*4 + c;
            size_t idx = ((size_t)b*NC + o)*NHW + n;
            out[idx] = x[idx] + bp[o] + acc[r][c];
        }
}

// ---------------- launch ------------------------------------------------------
extern "C" void kernel_launch(void* const* d_in, const int* in_sizes, int n_in,
                              void* d_out, int out_size){
    const float* x   = (const float*)d_in[0];
    const float* gsc = (const float*)d_in[1];
    const float* gbi = (const float*)d_in[2];
    const float* wq  = (const float*)d_in[3];  const float* bq = (const float*)d_in[4];
    const float* wk  = (const float*)d_in[5];  const float* bk = (const float*)d_in[6];
    const float* wv  = (const float*)d_in[7];  const float* bv = (const float*)d_in[8];
    const float* wp  = (const float*)d_in[9];  const float* bp = (const float*)d_in[10];
    const float* dq  = (const float*)d_in[11]; const float* zq = (const float*)d_in[12];
    const float* dk  = (const float*)d_in[13]; const float* zk = (const float*)d_in[14];
    const float* dv  = (const float*)d_in[15]; const float* zv = (const float*)d_in[16];
    const float* dw  = (const float*)d_in[17]; const float* zw = (const float*)d_in[18];
    float* out = (float*)d_out;

    void *pq, *pk, *pv, *pS, *pW, *pho;
    cudaGetSymbolAddress(&pq,  g_q);
    cudaGetSymbolAddress(&pk,  g_k);
    cudaGetSymbolAddress(&pv,  g_v);
    cudaGetSymbolAddress(&pS,  g_S);
    cudaGetSymbolAddress(&pW,  g_W);
    cudaGetSymbolAddress(&pho, g_ho);

    gn_kernel<<<NB*NG, 256>>>(x, gsc, gbi);
    qkv_kernel<<<dim3(NHW/64, NC/64, NB*3), 256>>>(wq, bq, wk, bk, wv, bv,
                                                   dq, zq, dk, zk, dv, zv);
    // S = q . k^T * (dq*dk/16)
    mma_nt<<<dim3(NHW/128, NHW/128, NB), 256>>>(
        (const __half*)pq, (const __half*)pk, (float*)pS,
        NHW, NHW, NC, NC, NC, NHW, dq, dk, 0.0625f);
    softmax_kernel<<<NB*NHW, 256>>>(dw, zw);
    // h_out[n][c] = W . v^T * (dv*dw)
    mma_nt<<<dim3(NHW/128, NC/128, NB), 256>>>(
        (const __half*)pW, (const __half*)pv, (float*)pho,
        NHW, NC, NHW, NHW, NHW, NC, dv, dw, 1.0f);
    proj_kernel<<<dim3(NHW/64, NC/64, NB), 256>>>(wp, bp, x, out);
}

// round 7
// speedup vs baseline: 1.2354x; 1.0333x over previous
#include <cuda_runtime.h>
#include <cuda_fp16.h>
#include <cstdint>

#define NB 4
#define NC 256
#define NHW 4096
#define NG 32
#define CPG (NC/NG)

// ---------------- scratch (static device globals; no allocation) -------------
__device__ float  g_h [(size_t)NB*NHW*NC];   // groupnorm out, [b][n][c]
__device__ __half g_q [(size_t)NB*NHW*NC];   // centered quant q, [b][n][c]
__device__ __half g_k [(size_t)NB*NHW*NC];   // centered quant k, [b][m][c]
__device__ __half g_v [(size_t)NB*NC*NHW];   // centered quant v, [b][c][m]
__device__ float  g_S [(size_t)NB*NHW*NHW];  // attn logits,     [b][n][m]
__device__ __half g_W [(size_t)NB*NHW*NHW];  // quant probs,     [b][n][m]
__device__ float  g_ho[(size_t)NB*NHW*NC];   // attn out,        [b][n][c]

// ---------------- helpers ----------------------------------------------------
__device__ __forceinline__ void cp16(void* sm, const void* gm){
    unsigned sa = (unsigned)__cvta_generic_to_shared(sm);
    asm volatile("cp.async.cg.shared.global [%0], [%1], 16;\n" :: "r"(sa), "l"(gm));
}
__device__ __forceinline__ void cp_commit(){ asm volatile("cp.async.commit_group;\n"); }
template<int N> __device__ __forceinline__ void cp_wait(){
    asm volatile("cp.async.wait_group %0;\n" :: "n"(N));
}
__device__ __forceinline__ void mma16816(float* c, const unsigned* a, const unsigned* b){
    asm volatile(
        "mma.sync.aligned.m16n8k16.row.col.f32.f16.f16.f32 "
        "{%0,%1,%2,%3}, {%4,%5,%6,%7}, {%8,%9}, {%0,%1,%2,%3};\n"
        : "+f"(c[0]), "+f"(c[1]), "+f"(c[2]), "+f"(c[3])
        : "r"(a[0]), "r"(a[1]), "r"(a[2]), "r"(a[3]), "r"(b[0]), "r"(b[1]));
}
__device__ __forceinline__ void ldsm4(unsigned& r0, unsigned& r1, unsigned& r2, unsigned& r3,
                                      unsigned addr){
    asm volatile("ldmatrix.sync.aligned.m8n8.x4.shared.b16 {%0,%1,%2,%3}, [%4];\n"
                 : "=r"(r0), "=r"(r1), "=r"(r2), "=r"(r3) : "r"(addr));
}

// ---------------- 1. GroupNorm (coalesced float4 stores) ---------------------
__global__ __launch_bounds__(256) void gn_kernel(const float* __restrict__ x,
                                                 const float* __restrict__ sc,
                                                 const float* __restrict__ bi){
    int b = blockIdx.x / NG, g = blockIdx.x % NG;
    const float* xp = x + ((size_t)b*NC + (size_t)g*CPG)*NHW;
    const int NE = CPG*NHW;
    float s = 0.f, s2 = 0.f;
    for (int i = threadIdx.x; i < NE; i += 256){ float v = xp[i]; s += v; s2 += v*v; }
    __shared__ float r1[256], r2[256];
    r1[threadIdx.x] = s; r2[threadIdx.x] = s2; __syncthreads();
    for (int o = 128; o > 0; o >>= 1){
        if (threadIdx.x < o){ r1[threadIdx.x] += r1[threadIdx.x+o]; r2[threadIdx.x] += r2[threadIdx.x+o]; }
        __syncthreads();
    }
    float mean = r1[0] / NE;
    float var  = r2[0] / NE - mean*mean;
    float rstd = rsqrtf(var + 1e-6f);
    float scv[CPG], biv[CPG];
    #pragma unroll
    for (int c = 0; c < CPG; c++){ scv[c] = sc[g*CPG + c]*rstd; biv[c] = bi[g*CPG + c]; }
    for (int n = threadIdx.x; n < NHW; n += 256){
        float vals[CPG];
        #pragma unroll
        for (int c = 0; c < CPG; c++)
            vals[c] = (xp[(size_t)c*NHW + n] - mean)*scv[c] + biv[c];
        float4* dst = (float4*)&g_h[((size_t)b*NHW + n)*NC + g*CPG];
        dst[0] = make_float4(vals[0], vals[1], vals[2], vals[3]);
        dst[1] = make_float4(vals[4], vals[5], vals[6], vals[7]);
    }
}

// ---------------- 2. QKV fp32 SGEMM-NT + quantize ---------------------------
__global__ __launch_bounds__(256) void qkv_kernel(
    const float* __restrict__ wq, const float* __restrict__ bq,
    const float* __restrict__ wk, const float* __restrict__ bk,
    const float* __restrict__ wv, const float* __restrict__ bv,
    const float* pdq, const float* pzq, const float* pdk, const float* pzk,
    const float* pdv, const float* pzv)
{
    int b = blockIdx.z / 3, which = blockIdx.z % 3;
    const float *Wt, *bias, *pd, *pz; __half* out;
    if (which == 0){ Wt = wq; bias = bq; pd = pdq; pz = pzq; out = g_q; }
    else if (which == 1){ Wt = wk; bias = bk; pd = pdk; pz = pzk; out = g_k; }
    else { Wt = wv; bias = bv; pd = pdv; pz = pzv; out = g_v; }
    const float* Ab = g_h + (size_t)b*NHW*NC;
    int n0 = blockIdx.x*64, o0 = blockIdx.y*64;
    __shared__ float As[64][17], Bs[64][17];
    float acc[4][4] = {};
    int tx = threadIdx.x & 15, ty = threadIdx.x >> 4;
    int lr = threadIdx.x >> 2, ls = threadIdx.x & 3;
    for (int k0 = 0; k0 < NC; k0 += 16){
        float4 va = *(const float4*)(Ab + (size_t)(n0+lr)*NC + k0 + ls*4);
        float4 vb = *(const float4*)(Wt + (size_t)(o0+lr)*NC + k0 + ls*4);
        As[lr][ls*4+0]=va.x; As[lr][ls*4+1]=va.y; As[lr][ls*4+2]=va.z; As[lr][ls*4+3]=va.w;
        Bs[lr][ls*4+0]=vb.x; Bs[lr][ls*4+1]=vb.y; Bs[lr][ls*4+2]=vb.z; Bs[lr][ls*4+3]=vb.w;
        __syncthreads();
        #pragma unroll
        for (int kk = 0; kk < 16; kk++){
            float a[4], bb[4];
            #pragma unroll
            for (int r = 0; r < 4; r++) a[r]  = As[ty*4+r][kk];
            #pragma unroll
            for (int c = 0; c < 4; c++) bb[c] = Bs[tx*4+c][kk];
            #pragma unroll
            for (int r = 0; r < 4; r++)
                #pragma unroll
                for (int c = 0; c < 4; c++) acc[r][c] += a[r]*bb[c];
        }
        __syncthreads();
    }
    float delta = pd[0], zp = pz[0];
    float inv = 1.f/delta, lo = -zp, hi = 255.f - zp;
    #pragma unroll
    for (int r = 0; r < 4; r++)
        #pragma unroll
        for (int c = 0; c < 4; c++){
            int n = n0 + ty*4 + r, o = o0 + tx*4 + c;
            float qv = acc[r][c] + bias[o];
            float iq = fminf(fmaxf(rintf(qv*inv), lo), hi);
            __half hv = __float2half_rn(iq);
            if (which < 2) out[((size_t)b*NHW + n)*NC + o] = hv;
            else           out[((size_t)b*NC  + o)*NHW + n] = hv;
        }
}

// ---------------- 3/5. HMMA NT GEMM, ldmatrix + 3-stage cp.async -------------
// C[i,j] = scale * sum_k A[i,k]*B[j,k];  A:[M][lda], B:[N][ldb], C:[M][ldc]
#define MM_STAGES 3
#define MM_LDS 40                      // halfs per smem row (32 + 8 pad)
#define MM_STAGE_HALFS (128*MM_LDS)    // per tensor per stage
__global__ __launch_bounds__(256) void mma_nt(
    const __half* __restrict__ Ag, const __half* __restrict__ Bg, float* __restrict__ Cg,
    int M, int N, int K, int lda, int ldb, int ldc,
    const float* sa, const float* sb, float smul)
{
    extern __shared__ __align__(16) __half smem[];
    __half* As = smem;                               // [stage][128][MM_LDS]
    __half* Bs = smem + MM_STAGES*MM_STAGE_HALFS;
    int bz = blockIdx.z;
    const __half* A  = Ag + (size_t)bz*M*lda;
    const __half* Bp = Bg + (size_t)bz*N*ldb;
    float*        Cp = Cg + (size_t)bz*M*ldc;
    int m0 = blockIdx.x*128, n0 = blockIdx.y*128;
    int tid = threadIdx.x, lane = tid & 31, warp = tid >> 5;
    int wm = warp >> 1, wn = warp & 1;          // 4 x 2 warp grid, 32x64 per warp
    int r = lane >> 2, cq = (lane & 3)*2;

    // ldmatrix per-lane byte offsets (within a stage, before kk offset)
    int lt = lane >> 3, l7 = lane & 7;
    // A fragment tiles for m16 block i: rows (t&1)*8 + l7, cols (t>>1)*8
    unsigned aoff[2];
    #pragma unroll
    for (int i = 0; i < 2; i++)
        aoff[i] = ((wm*32 + i*16 + (lt&1)*8 + l7)*MM_LDS + (lt>>1)*8)*2;
    // B fragment tiles for n8-pair jj: rows (t>>1)*8 + l7 (+jj*16), cols (t&1)*8
    unsigned boff[4];
    #pragma unroll
    for (int jj = 0; jj < 4; jj++)
        boff[jj] = ((wn*64 + jj*16 + (lt>>1)*8 + l7)*MM_LDS + (lt&1)*8)*2;

    unsigned asBase = (unsigned)__cvta_generic_to_shared(As);
    unsigned bsBase = (unsigned)__cvta_generic_to_shared(Bs);

    float acc[2][8][4];
    #pragma unroll
    for (int i = 0; i < 2; i++)
        #pragma unroll
        for (int j = 0; j < 8; j++)
            #pragma unroll
            for (int t = 0; t < 4; t++) acc[i][j][t] = 0.f;

    int KT = K/32;
    auto prefetch = [&](int kt, int buf){
        int k0 = kt*32;
        __half* Ab_ = As + buf*MM_STAGE_HALFS;
        __half* Bb_ = Bs + buf*MM_STAGE_HALFS;
        #pragma unroll
        for (int it = 0; it < 2; ++it){
            int flat = tid + it*256;
            int row = flat >> 2, seg = flat & 3;
            cp16(Ab_ + row*MM_LDS + seg*8, A  + (size_t)(m0+row)*lda + k0 + seg*8);
            cp16(Bb_ + row*MM_LDS + seg*8, Bp + (size_t)(n0+row)*ldb + k0 + seg*8);
        }
        cp_commit();
    };

    prefetch(0, 0);
    prefetch(1, 1);
    for (int kt = 0; kt < KT; ++kt){
        int cur = kt % MM_STAGES;
        cp_wait<1>();
        __syncthreads();
        if (kt + 2 < KT) prefetch(kt+2, (kt+2) % MM_STAGES);
        unsigned aS = asBase + cur*MM_STAGE_HALFS*2;
        unsigned bS = bsBase + cur*MM_STAGE_HALFS*2;
        #pragma unroll
        for (int kk = 0; kk < 32; kk += 16){
            unsigned af[2][4], bf[8][2];
            #pragma unroll
            for (int i = 0; i < 2; i++)
                ldsm4(af[i][0], af[i][1], af[i][2], af[i][3], aS + aoff[i] + kk*2);
            #pragma unroll
            for (int jj = 0; jj < 4; jj++)
                ldsm4(bf[2*jj][0], bf[2*jj][1], bf[2*jj+1][0], bf[2*jj+1][1],
                      bS + boff[jj] + kk*2);
            #pragma unroll
            for (int i = 0; i < 2; i++)
                #pragma unroll
                for (int j = 0; j < 8; j++) mma16816(acc[i][j], af[i], bf[j]);
        }
    }
    float scale = sa[0]*sb[0]*smul;
    #pragma unroll
    for (int i = 0; i < 2; i++)
        #pragma unroll
        for (int j = 0; j < 8; j++){
            int row = m0 + wm*32 + i*16 + r;
            int col = n0 + wn*64 + j*8 + cq;
            float2 v0 = make_float2(acc[i][j][0]*scale, acc[i][j][1]*scale);
            float2 v1 = make_float2(acc[i][j][2]*scale, acc[i][j][3]*scale);
            *(float2*)(Cp + (size_t)row*ldc + col)     = v0;
            *(float2*)(Cp + (size_t)(row+8)*ldc + col) = v1;
        }
}

// ---------------- 4. softmax + prob quantization (register-resident) ---------
__global__ __launch_bounds__(256) void softmax_kernel(const float* pdw, const float* pzw){
    size_t rowi = blockIdx.x;                  // b*NHW + n
    const float4* S4 = (const float4*)(g_S + rowi*NHW);
    __half*       Wp = g_W + rowi*NHW;
    int tid = threadIdx.x, lane = tid & 31, wid = tid >> 5;
    __shared__ float redm[8], reds[8];

    float4 v[4];
    #pragma unroll
    for (int i = 0; i < 4; i++) v[i] = S4[tid + 256*i];

    float mx = -1e30f;
    #pragma unroll
    for (int i = 0; i < 4; i++){
        mx = fmaxf(mx, fmaxf(fmaxf(v[i].x, v[i].y), fmaxf(v[i].z, v[i].w)));
    }
    #pragma unroll
    for (int o = 16; o > 0; o >>= 1) mx = fmaxf(mx, __shfl_xor_sync(0xffffffffu, mx, o));
    if (lane == 0) redm[wid] = mx;
    __syncthreads();
    mx = redm[0];
    #pragma unroll
    for (int w = 1; w < 8; w++) mx = fmaxf(mx, redm[w]);

    float sum = 0.f;
    #pragma unroll
    for (int i = 0; i < 4; i++){
        v[i].x = __expf(v[i].x - mx); sum += v[i].x;
        v[i].y = __expf(v[i].y - mx); sum += v[i].y;
        v[i].z = __expf(v[i].z - mx); sum += v[i].z;
        v[i].w = __expf(v[i].w - mx); sum += v[i].w;
    }
    #pragma unroll
    for (int o = 16; o > 0; o >>= 1) sum += __shfl_xor_sync(0xffffffffu, sum, o);
    if (lane == 0) reds[wid] = sum;
    __syncthreads();
    float total = reds[0];
    #pragma unroll
    for (int w = 1; w < 8; w++) total += reds[w];

    float dwv = pdw[0], zwv = pzw[0];
    float inv = 1.f/(total*dwv);
    float lo = -zwv, hi = 255.f - zwv;
    #pragma unroll
    for (int i = 0; i < 4; i++){
        __half h0 = __float2half_rn(fminf(fmaxf(rintf(v[i].x*inv), lo), hi));
        __half h1 = __float2half_rn(fminf(fmaxf(rintf(v[i].y*inv), lo), hi));
        __half h2 = __float2half_rn(fminf(fmaxf(rintf(v[i].z*inv), lo), hi));
        __half h3 = __float2half_rn(fminf(fmaxf(rintf(v[i].w*inv), lo), hi));
        __half2 p0 = __halves2half2(h0, h1);
        __half2 p1 = __halves2half2(h2, h3);
        uint2 pk;
        pk.x = *(unsigned*)&p0;
        pk.y = *(unsigned*)&p1;
        *(uint2*)(Wp + 4*tid + 1024*i) = pk;
    }
}

// ---------------- 6. proj + bias + residual ----------------------------------
__global__ __launch_bounds__(256) void proj_kernel(
    const float* __restrict__ wp, const float* __restrict__ bp,
    const float* __restrict__ x, float* __restrict__ out)
{
    int b = blockIdx.z;
    const float* Bb = g_ho + (size_t)b*NHW*NC;
    int n0 = blockIdx.x*64, o0 = blockIdx.y*64;
    __shared__ float As[64][17], Bs[64][17];
    float acc[4][4] = {};
    int tx = threadIdx.x & 15, ty = threadIdx.x >> 4;
    int lr = threadIdx.x >> 2, ls = threadIdx.x & 3;
    for (int k0 = 0; k0 < NC; k0 += 16){
        float4 va = *(const float4*)(wp + (size_t)(o0+lr)*NC + k0 + ls*4);
        float4 vb = *(const float4*)(Bb + (size_t)(n0+lr)*NC + k0 + ls*4);
        As[lr][ls*4+0]=va.x; As[lr][ls*4+1]=va.y; As[lr][ls*4+2]=va.z; As[lr][ls*4+3]=va.w;
        Bs[lr][ls*4+0]=vb.x; Bs[lr][ls*4+1]=vb.y; Bs[lr][ls*4+2]=vb.z; Bs[lr][ls*4+3]=vb.w;
        __syncthreads();
        #pragma unroll
        for (int kk = 0; kk < 16; kk++){
            float a[4], bb[4];
            #pragma unroll
            for (int r = 0; r < 4; r++) a[r]  = As[ty*4+r][kk];
            #pragma unroll
            for (int c = 0; c < 4; c++) bb[c] = Bs[tx*4+c][kk];
            #pragma unroll
            for (int r = 0; r < 4; r++)
                #pragma unroll
                for (int c = 0; c < 4; c++) acc[r][c] += a[r]*bb[c];
        }
        __syncthreads();
    }
    #pragma unroll
    for (int r = 0; r < 4; r++)
        #pragma unroll
        for (int c = 0; c < 4; c++){
            int o = o0 + ty*4 + r, n = n0 + tx*4 + c;
            size_t idx = ((size_t)b*NC + o)*NHW + n;
            out[idx] = x[idx] + bp[o] + acc[r][c];
        }
}

// ---------------- launch ------------------------------------------------------
extern "C" void kernel_launch(void* const* d_in, const int* in_sizes, int n_in,
                              void* d_out, int out_size){
    const float* x   = (const float*)d_in[0];
    const float* gsc = (const float*)d_in[1];
    const float* gbi = (const float*)d_in[2];
    const float* wq  = (const float*)d_in[3];  const float* bq = (const float*)d_in[4];
    const float* wk  = (const float*)d_in[5];  const float* bk = (const float*)d_in[6];
    const float* wv  = (const float*)d_in[7];  const float* bv = (const float*)d_in[8];
    const float* wp  = (const float*)d_in[9];  const float* bp = (const float*)d_in[10];
    const float* dq  = (const float*)d_in[11]; const float* zq = (const float*)d_in[12];
    const float* dk  = (const float*)d_in[13]; const float* zk = (const float*)d_in[14];
    const float* dv  = (const float*)d_in[15]; const float* zv = (const float*)d_in[16];
    const float* dw  = (const float*)d_in[17]; const float* zw = (const float*)d_in[18];
    float* out = (float*)d_out;

    void *pq, *pk, *pv, *pS, *pW, *pho;
    cudaGetSymbolAddress(&pq,  g_q);
    cudaGetSymbolAddress(&pk,  g_k);
    cudaGetSymbolAddress(&pv,  g_v);
    cudaGetSymbolAddress(&pS,  g_S);
    cudaGetSymbolAddress(&pW,  g_W);
    cudaGetSymbolAddress(&pho, g_ho);

    const int mm_smem = MM_STAGES*MM_STAGE_HALFS*2*2;   // A+B, bytes (=61440)
    cudaFuncSetAttribute(mma_nt, cudaFuncAttributeMaxDynamicSharedMemorySize, mm_smem);

    gn_kernel<<<NB*NG, 256>>>(x, gsc, gbi);
    qkv_kernel<<<dim3(NHW/64, NC/64, NB*3), 256>>>(wq, bq, wk, bk, wv, bv,
                                                   dq, zq, dk, zk, dv, zv);
    // S = q . k^T * (dq*dk/16)
    mma_nt<<<dim3(NHW/128, NHW/128, NB), 256, mm_smem>>>(
        (const __half*)pq, (const __half*)pk, (float*)pS,
        NHW, NHW, NC, NC, NC, NHW, dq, dk, 0.0625f);
    softmax_kernel<<<NB*NHW, 256>>>(dw, zw);
    // h_out[n][c] = W . v^T * (dv*dw)
    mma_nt<<<dim3(NHW/128, NC/128, NB), 256, mm_smem>>>(
        (const __half*)pW, (const __half*)pv, (float*)pho,
        NHW, NC, NHW, NHW, NHW, NC, dv, dw, 1.0f);
    proj_kernel<<<dim3(NHW/64, NC/64, NB), 256>>>(wp, bp, x, out);
}

// round 10
// speedup vs baseline: 1.5810x; 1.2797x over previous
#include <cuda_runtime.h>
#include <cuda_fp16.h>
#include <cstdint>

#define NB 4
#define NC 256
#define NHW 4096
#define NG 32
#define CPG (NC/NG)

// ---------------- scratch (static device globals; no allocation) -------------
__device__ __half g_hhi[(size_t)NB*NHW*NC];  // groupnorm out hi, [b][n][c]
__device__ __half g_hlo[(size_t)NB*NHW*NC];  // groupnorm out lo residual
__device__ __half g_whi[3*NC*NC];            // wq/wk/wv hi
__device__ __half g_wlo[3*NC*NC];            // wq/wk/wv lo residual
__device__ __half g_q [(size_t)NB*NHW*NC];   // centered quant q, [b][n][c]
__device__ __half g_k [(size_t)NB*NHW*NC];   // centered quant k, [b][m][c]
__device__ __half g_v [(size_t)NB*NC*NHW];   // centered quant v, [b][c][m]
__device__ float  g_S [(size_t)NB*NHW*NHW];  // attn logits,     [b][n][m]
__device__ __half g_W [(size_t)NB*NHW*NHW];  // quant probs,     [b][n][m]
__device__ float  g_ho[(size_t)NB*NHW*NC];   // attn out,        [b][n][c]

// ---------------- helpers ----------------------------------------------------
__device__ __forceinline__ void cp16(void* sm, const void* gm){
    unsigned sa = (unsigned)__cvta_generic_to_shared(sm);
    asm volatile("cp.async.cg.shared.global [%0], [%1], 16;\n" :: "r"(sa), "l"(gm));
}
__device__ __forceinline__ void cp_commit(){ asm volatile("cp.async.commit_group;\n"); }
template<int N> __device__ __forceinline__ void cp_wait(){
    asm volatile("cp.async.wait_group %0;\n" :: "n"(N));
}
__device__ __forceinline__ void mma16816(float* c, const unsigned* a, const unsigned* b){
    asm volatile(
        "mma.sync.aligned.m16n8k16.row.col.f32.f16.f16.f32 "
        "{%0,%1,%2,%3}, {%4,%5,%6,%7}, {%8,%9}, {%0,%1,%2,%3};\n"
        : "+f"(c[0]), "+f"(c[1]), "+f"(c[2]), "+f"(c[3])
        : "r"(a[0]), "r"(a[1]), "r"(a[2]), "r"(a[3]), "r"(b[0]), "r"(b[1]));
}
__device__ __forceinline__ void ldsm4(unsigned& r0, unsigned& r1, unsigned& r2, unsigned& r3,
                                      unsigned addr){
    asm volatile("ldmatrix.sync.aligned.m8n8.x4.shared.b16 {%0,%1,%2,%3}, [%4];\n"
                 : "=r"(r0), "=r"(r1), "=r"(r2), "=r"(r3) : "r"(addr));
}

// ---------------- 0. weight split prep ---------------------------------------
__global__ __launch_bounds__(256) void wsplit_kernel(const float* __restrict__ wq,
                                                     const float* __restrict__ wk,
                                                     const float* __restrict__ wv){
    int i = blockIdx.x*256 + threadIdx.x;            // 0..65535
    const float* src[3] = {wq, wk, wv};
    #pragma unroll
    for (int w = 0; w < 3; w++){
        float v = src[w][i];
        __half hi = __float2half_rn(v);
        __half lo = __float2half_rn(v - __half2float(hi));
        g_whi[w*NC*NC + i] = hi;
        g_wlo[w*NC*NC + i] = lo;
    }
}

// ---------------- 1. GroupNorm -> split fp16 hi/lo ----------------------------
__global__ __launch_bounds__(256) void gn_kernel(const float* __restrict__ x,
                                                 const float* __restrict__ sc,
                                                 const float* __restrict__ bi){
    int b = blockIdx.x / NG, g = blockIdx.x % NG;
    const float* xp = x + ((size_t)b*NC + (size_t)g*CPG)*NHW;
    const int NE = CPG*NHW;
    float s = 0.f, s2 = 0.f;
    for (int i = threadIdx.x; i < NE; i += 256){ float v = xp[i]; s += v; s2 += v*v; }
    __shared__ float r1[256], r2[256];
    r1[threadIdx.x] = s; r2[threadIdx.x] = s2; __syncthreads();
    for (int o = 128; o > 0; o >>= 1){
        if (threadIdx.x < o){ r1[threadIdx.x] += r1[threadIdx.x+o]; r2[threadIdx.x] += r2[threadIdx.x+o]; }
        __syncthreads();
    }
    float mean = r1[0] / NE;
    float var  = r2[0] / NE - mean*mean;
    float rstd = rsqrtf(var + 1e-6f);
    float scv[CPG], biv[CPG];
    #pragma unroll
    for (int c = 0; c < CPG; c++){ scv[c] = sc[g*CPG + c]*rstd; biv[c] = bi[g*CPG + c]; }
    for (int n = threadIdx.x; n < NHW; n += 256){
        __half hh[CPG], hl[CPG];
        #pragma unroll
        for (int c = 0; c < CPG; c++){
            float v = (xp[(size_t)c*NHW + n] - mean)*scv[c] + biv[c];
            hh[c] = __float2half_rn(v);
            hl[c] = __float2half_rn(v - __half2float(hh[c]));
        }
        size_t base = ((size_t)b*NHW + n)*NC + g*CPG;
        *(uint4*)&g_hhi[base] = *(uint4*)hh;     // 8 halfs = 16B coalesced
        *(uint4*)&g_hlo[base] = *(uint4*)hl;
    }
}

// ---------------- 2. QKV tensor-core GEMM (fp16-split) + quantize ------------
// C[n][o] = sum_c h[n][c]*w[o][c] = Ahi.Bhi + Ahi.Blo + Alo.Bhi  (exact to 2^-22)
#define QK_LDS 40
#define QK_TILE (128*QK_LDS)            // halfs per tensor per stage
__global__ __launch_bounds__(256) void qkv_mma(
    const float* __restrict__ bq, const float* __restrict__ bk, const float* __restrict__ bv,
    const float* pdq, const float* pzq, const float* pdk, const float* pzk,
    const float* pdv, const float* pzv)
{
    extern __shared__ __align__(16) __half smem[];   // [2][4][128][QK_LDS]
    int b = blockIdx.z / 3, which = blockIdx.z % 3;
    const float *bias, *pd, *pz; __half* out;
    if (which == 0){ bias = bq; pd = pdq; pz = pzq; out = g_q; }
    else if (which == 1){ bias = bk; pd = pdk; pz = pzk; out = g_k; }
    else { bias = bv; pd = pdv; pz = pzv; out = g_v; }
    const __half* Ahi = g_hhi + (size_t)b*NHW*NC;
    const __half* Alo = g_hlo + (size_t)b*NHW*NC;
    const __half* Bhi = g_whi + which*NC*NC;
    const __half* Blo = g_wlo + which*NC*NC;

    int m0 = blockIdx.x*128, n0 = blockIdx.y*128;
    int tid = threadIdx.x, lane = tid & 31, warp = tid >> 5;
    int wm = warp >> 1, wn = warp & 1;
    int r = lane >> 2, cq = (lane & 3)*2;
    int lt = lane >> 3, l7 = lane & 7;
    unsigned aoff[2];
    #pragma unroll
    for (int i = 0; i < 2; i++)
        aoff[i] = ((wm*32 + i*16 + (lt&1)*8 + l7)*QK_LDS + (lt>>1)*8)*2;
    unsigned boff[4];
    #pragma unroll
    for (int jj = 0; jj < 4; jj++)
        boff[jj] = ((wn*64 + jj*16 + (lt>>1)*8 + l7)*QK_LDS + (lt&1)*8)*2;
    unsigned smBase = (unsigned)__cvta_generic_to_shared(smem);

    float acc[2][8][4];
    #pragma unroll
    for (int i = 0; i < 2; i++)
        #pragma unroll
        for (int j = 0; j < 8; j++)
            #pragma unroll
            for (int t = 0; t < 4; t++) acc[i][j][t] = 0.f;

    const __half* srcs[4] = {Ahi, Alo, Bhi, Blo};
    int KT = NC/32;                                   // 8
    auto prefetch = [&](int kt, int buf){
        int k0 = kt*32;
        #pragma unroll
        for (int t = 0; t < 4; t++){
            int rowbase = (t < 2) ? m0 : n0;
            __half* dst = smem + (buf*4 + t)*QK_TILE;
            #pragma unroll
            for (int it = 0; it < 2; ++it){
                int flat = tid + it*256;
                int row = flat >> 2, seg = flat & 3;
                cp16(dst + row*QK_LDS + seg*8,
                     srcs[t] + (size_t)(rowbase+row)*NC + k0 + seg*8);
            }
        }
        cp_commit();
    };

    prefetch(0, 0);
    for (int kt = 0; kt < KT; ++kt){
        int cur = kt & 1;
        if (kt + 1 < KT){ prefetch(kt+1, cur^1); cp_wait<1>(); }
        else            cp_wait<0>();
        __syncthreads();
        unsigned aHi = smBase + (cur*4 + 0)*QK_TILE*2;
        unsigned aLo = smBase + (cur*4 + 1)*QK_TILE*2;
        unsigned bHi = smBase + (cur*4 + 2)*QK_TILE*2;
        unsigned bLo = smBase + (cur*4 + 3)*QK_TILE*2;
        #pragma unroll
        for (int kk = 0; kk < 32; kk += 16){
            unsigned afh[2][4], afl[2][4], bfh[8][2], bfl[8][2];
            #pragma unroll
            for (int i = 0; i < 2; i++){
                ldsm4(afh[i][0], afh[i][1], afh[i][2], afh[i][3], aHi + aoff[i] + kk*2);
                ldsm4(afl[i][0], afl[i][1], afl[i][2], afl[i][3], aLo + aoff[i] + kk*2);
            }
            #pragma unroll
            for (int jj = 0; jj < 4; jj++){
                ldsm4(bfh[2*jj][0], bfh[2*jj][1], bfh[2*jj+1][0], bfh[2*jj+1][1],
                      bHi + boff[jj] + kk*2);
                ldsm4(bfl[2*jj][0], bfl[2*jj][1], bfl[2*jj+1][0], bfl[2*jj+1][1],
                      bLo + boff[jj] + kk*2);
            }
            #pragma unroll
            for (int i = 0; i < 2; i++)
                #pragma unroll
                for (int j = 0; j < 8; j++){
                    mma16816(acc[i][j], afh[i], bfh[j]);
                    mma16816(acc[i][j], afh[i], bfl[j]);
                    mma16816(acc[i][j], afl[i], bfh[j]);
                }
        }
        __syncthreads();
    }

    float delta = pd[0], zp = pz[0];
    float inv = 1.f/delta, qlo = -zp, qhi = 255.f - zp;
    #pragma unroll
    for (int i = 0; i < 2; i++)
        #pragma unroll
        for (int j = 0; j < 8; j++){
            int n  = m0 + wm*32 + i*16 + r;
            int o  = n0 + wn*64 + j*8 + cq;
            float b0 = bias[o], b1 = bias[o+1];
            float v00 = fminf(fmaxf(rintf((acc[i][j][0]+b0)*inv), qlo), qhi);
            float v01 = fminf(fmaxf(rintf((acc[i][j][1]+b1)*inv), qlo), qhi);
            float v10 = fminf(fmaxf(rintf((acc[i][j][2]+b0)*inv), qlo), qhi);
            float v11 = fminf(fmaxf(rintf((acc[i][j][3]+b1)*inv), qlo), qhi);
            if (which < 2){
                __half2 p0 = __halves2half2(__float2half_rn(v00), __float2half_rn(v01));
                __half2 p1 = __halves2half2(__float2half_rn(v10), __float2half_rn(v11));
                *(__half2*)&out[((size_t)b*NHW + n  )*NC + o] = p0;
                *(__half2*)&out[((size_t)b*NHW + n+8)*NC + o] = p1;
            } else {
                out[((size_t)b*NC + o  )*NHW + n  ] = __float2half_rn(v00);
                out[((size_t)b*NC + o+1)*NHW + n  ] = __float2half_rn(v01);
                out[((size_t)b*NC + o  )*NHW + n+8] = __float2half_rn(v10);
                out[((size_t)b*NC + o+1)*NHW + n+8] = __float2half_rn(v11);
            }
        }
}

// ---------------- 3/5. HMMA NT GEMM, ldmatrix + 3-stage cp.async -------------
#define MM_STAGES 3
#define MM_LDS 40
#define MM_STAGE_HALFS (128*MM_LDS)
__global__ __launch_bounds__(256) void mma_nt(
    const __half* __restrict__ Ag, const __half* __restrict__ Bg, float* __restrict__ Cg,
    int M, int N, int K, int lda, int ldb, int ldc,
    const float* sa, const float* sb, float smul)
{
    extern __shared__ __align__(16) __half smem[];
    __half* As = smem;
    __half* Bs = smem + MM_STAGES*MM_STAGE_HALFS;
    int bz = blockIdx.z;
    const __half* A  = Ag + (size_t)bz*M*lda;
    const __half* Bp = Bg + (size_t)bz*N*ldb;
    float*        Cp = Cg + (size_t)bz*M*ldc;
    int m0 = blockIdx.x*128, n0 = blockIdx.y*128;
    int tid = threadIdx.x, lane = tid & 31, warp = tid >> 5;
    int wm = warp >> 1, wn = warp & 1;
    int r = lane >> 2, cq = (lane & 3)*2;
    int lt = lane >> 3, l7 = lane & 7;
    unsigned aoff[2];
    #pragma unroll
    for (int i = 0; i < 2; i++)
        aoff[i] = ((wm*32 + i*16 + (lt&1)*8 + l7)*MM_LDS + (lt>>1)*8)*2;
    unsigned boff[4];
    #pragma unroll
    for (int jj = 0; jj < 4; jj++)
        boff[jj] = ((wn*64 + jj*16 + (lt>>1)*8 + l7)*MM_LDS + (lt&1)*8)*2;
    unsigned asBase = (unsigned)__cvta_generic_to_shared(As);
    unsigned bsBase = (unsigned)__cvta_generic_to_shared(Bs);

    float acc[2][8][4];
    #pragma unroll
    for (int i = 0; i < 2; i++)
        #pragma unroll
        for (int j = 0; j < 8; j++)
            #pragma unroll
            for (int t = 0; t < 4; t++) acc[i][j][t] = 0.f;

    int KT = K/32;
    auto prefetch = [&](int kt, int buf){
        int k0 = kt*32;
        __half* Ab_ = As + buf*MM_STAGE_HALFS;
        __half* Bb_ = Bs + buf*MM_STAGE_HALFS;
        #pragma unroll
        for (int it = 0; it < 2; ++it){
            int flat = tid + it*256;
            int row = flat >> 2, seg = flat & 3;
            cp16(Ab_ + row*MM_LDS + seg*8, A  + (size_t)(m0+row)*lda + k0 + seg*8);
            cp16(Bb_ + row*MM_LDS + seg*8, Bp + (size_t)(n0+row)*ldb + k0 + seg*8);
        }
        cp_commit();
    };

    prefetch(0, 0);
    prefetch(1, 1);
    for (int kt = 0; kt < KT; ++kt){
        int cur = kt % MM_STAGES;
        cp_wait<1>();
        __syncthreads();
        if (kt + 2 < KT) prefetch(kt+2, (kt+2) % MM_STAGES);
        unsigned aS = asBase + cur*MM_STAGE_HALFS*2;
        unsigned bS = bsBase + cur*MM_STAGE_HALFS*2;
        #pragma unroll
        for (int kk = 0; kk < 32; kk += 16){
            unsigned af[2][4], bf[8][2];
            #pragma unroll
            for (int i = 0; i < 2; i++)
                ldsm4(af[i][0], af[i][1], af[i][2], af[i][3], aS + aoff[i] + kk*2);
            #pragma unroll
            for (int jj = 0; jj < 4; jj++)
                ldsm4(bf[2*jj][0], bf[2*jj][1], bf[2*jj+1][0], bf[2*jj+1][1],
                      bS + boff[jj] + kk*2);
            #pragma unroll
            for (int i = 0; i < 2; i++)
                #pragma unroll
                for (int j = 0; j < 8; j++) mma16816(acc[i][j], af[i], bf[j]);
        }
    }
    float scale = sa[0]*sb[0]*smul;
    #pragma unroll
    for (int i = 0; i < 2; i++)
        #pragma unroll
        for (int j = 0; j < 8; j++){
            int row = m0 + wm*32 + i*16 + r;
            int col = n0 + wn*64 + j*8 + cq;
            float2 v0 = make_float2(acc[i][j][0]*scale, acc[i][j][1]*scale);
            float2 v1 = make_float2(acc[i][j][2]*scale, acc[i][j][3]*scale);
            *(float2*)(Cp + (size_t)row*ldc + col)     = v0;
            *(float2*)(Cp + (size_t)(row+8)*ldc + col) = v1;
        }
}

// ---------------- 4. softmax + prob quantization (register-resident) ---------
__global__ __launch_bounds__(256) void softmax_kernel(const float* pdw, const float* pzw){
    size_t rowi = blockIdx.x;
    const float4* S4 = (const float4*)(g_S + rowi*NHW);
    __half*       Wp = g_W + rowi*NHW;
    int tid = threadIdx.x, lane = tid & 31, wid = tid >> 5;
    __shared__ float redm[8], reds[8];

    float4 v[4];
    #pragma unroll
    for (int i = 0; i < 4; i++) v[i] = S4[tid + 256*i];

    float mx = -1e30f;
    #pragma unroll
    for (int i = 0; i < 4; i++){
        mx = fmaxf(mx, fmaxf(fmaxf(v[i].x, v[i].y), fmaxf(v[i].z, v[i].w)));
    }
    #pragma unroll
    for (int o = 16; o > 0; o >>= 1) mx = fmaxf(mx, __shfl_xor_sync(0xffffffffu, mx, o));
    if (lane == 0) redm[wid] = mx;
    __syncthreads();
    mx = redm[0];
    #pragma unroll
    for (int w = 1; w < 8; w++) mx = fmaxf(mx, redm[w]);

    float sum = 0.f;
    #pragma unroll
    for (int i = 0; i < 4; i++){
        v[i].x = __expf(v[i].x - mx); sum += v[i].x;
        v[i].y = __expf(v[i].y - mx); sum += v[i].y;
        v[i].z = __expf(v[i].z - mx); sum += v[i].z;
        v[i].w = __expf(v[i].w - mx); sum += v[i].w;
    }
    #pragma unroll
    for (int o = 16; o > 0; o >>= 1) sum += __shfl_xor_sync(0xffffffffu, sum, o);
    if (lane == 0) reds[wid] = sum;
    __syncthreads();
    float total = reds[0];
    #pragma unroll
    for (int w = 1; w < 8; w++) total += reds[w];

    float dwv = pdw[0], zwv = pzw[0];
    float inv = 1.f/(total*dwv);
    float lo = -zwv, hi = 255.f - zwv;
    #pragma unroll
    for (int i = 0; i < 4; i++){
        __half h0 = __float2half_rn(fminf(fmaxf(rintf(v[i].x*inv), lo), hi));
        __half h1 = __float2half_rn(fminf(fmaxf(rintf(v[i].y*inv), lo), hi));
        __half h2 = __float2half_rn(fminf(fmaxf(rintf(v[i].z*inv), lo), hi));
        __half h3 = __float2half_rn(fminf(fmaxf(rintf(v[i].w*inv), lo), hi));
        __half2 p0 = __halves2half2(h0, h1);
        __half2 p1 = __halves2half2(h2, h3);
        uint2 pk;
        pk.x = *(unsigned*)&p0;
        pk.y = *(unsigned*)&p1;
        *(uint2*)(Wp + 4*tid + 1024*i) = pk;
    }
}

// ---------------- 6. proj + bias + residual ----------------------------------
__global__ __launch_bounds__(256) void proj_kernel(
    const float* __restrict__ wp, const float* __restrict__ bp,
    const float* __restrict__ x, float* __restrict__ out)
{
    int b = blockIdx.z;
    const float* Bb = g_ho + (size_t)b*NHW*NC;
    int n0 = blockIdx.x*64, o0 = blockIdx.y*64;
    __shared__ float As[64][17], Bs[64][17];
    float acc[4][4] = {};
    int tx = threadIdx.x & 15, ty = threadIdx.x >> 4;
    int lr = threadIdx.x >> 2, ls = threadIdx.x & 3;
    for (int k0 = 0; k0 < NC; k0 += 16){
        float4 va = *(const float4*)(wp + (size_t)(o0+lr)*NC + k0 + ls*4);
        float4 vb = *(const float4*)(Bb + (size_t)(n0+lr)*NC + k0 + ls*4);
        As[lr][ls*4+0]=va.x; As[lr][ls*4+1]=va.y; As[lr][ls*4+2]=va.z; As[lr][ls*4+3]=va.w;
        Bs[lr][ls*4+0]=vb.x; Bs[lr][ls*4+1]=vb.y; Bs[lr][ls*4+2]=vb.z; Bs[lr][ls*4+3]=vb.w;
        __syncthreads();
        #pragma unroll
        for (int kk = 0; kk < 16; kk++){
            float a[4], bb[4];
            #pragma unroll
            for (int r = 0; r < 4; r++) a[r]  = As[ty*4+r][kk];
            #pragma unroll
            for (int c = 0; c < 4; c++) bb[c] = Bs[tx*4+c][kk];
            #pragma unroll
            for (int r = 0; r < 4; r++)
                #pragma unroll
                for (int c = 0; c < 4; c++) acc[r][c] += a[r]*bb[c];
        }
        __syncthreads();
    }
    #pragma unroll
    for (int r = 0; r < 4; r++)
        #pragma unroll
        for (int c = 0; c < 4; c++){
            int o = o0 + ty*4 + r, n = n0 + tx*4 + c;
            size_t idx = ((size_t)b*NC + o)*NHW + n;
            out[idx] = x[idx] + bp[o] + acc[r][c];
        }
}

// ---------------- launch ------------------------------------------------------
extern "C" void kernel_launch(void* const* d_in, const int* in_sizes, int n_in,
                              void* d_out, int out_size){
    const float* x   = (const float*)d_in[0];
    const float* gsc = (const float*)d_in[1];
    const float* gbi = (const float*)d_in[2];
    const float* wq  = (const float*)d_in[3];  const float* bq = (const float*)d_in[4];
    const float* wk  = (const float*)d_in[5];  const float* bk = (const float*)d_in[6];
    const float* wv  = (const float*)d_in[7];  const float* bv = (const float*)d_in[8];
    const float* wp  = (const float*)d_in[9];  const float* bp = (const float*)d_in[10];
    const float* dq  = (const float*)d_in[11]; const float* zq = (const float*)d_in[12];
    const float* dk  = (const float*)d_in[13]; const float* zk = (const float*)d_in[14];
    const float* dv  = (const float*)d_in[15]; const float* zv = (const float*)d_in[16];
    const float* dw  = (const float*)d_in[17]; const float* zw = (const float*)d_in[18];
    float* out = (float*)d_out;

    void *pq, *pk, *pv, *pS, *pW, *pho;
    cudaGetSymbolAddress(&pq,  g_q);
    cudaGetSymbolAddress(&pk,  g_k);
    cudaGetSymbolAddress(&pv,  g_v);
    cudaGetSymbolAddress(&pS,  g_S);
    cudaGetSymbolAddress(&pW,  g_W);
    cudaGetSymbolAddress(&pho, g_ho);

    const int mm_smem = MM_STAGES*MM_STAGE_HALFS*2*2;   // 61440 B
    cudaFuncSetAttribute(mma_nt, cudaFuncAttributeMaxDynamicSharedMemorySize, mm_smem);
    const int qk_smem = 2*4*QK_TILE*2;                  // 81920 B
    cudaFuncSetAttribute(qkv_mma, cudaFuncAttributeMaxDynamicSharedMemorySize, qk_smem);

    wsplit_kernel<<<NC*NC/256, 256>>>(wq, wk, wv);
    gn_kernel<<<NB*NG, 256>>>(x, gsc, gbi);
    qkv_mma<<<dim3(NHW/128, NC/128, NB*3), 256, qk_smem>>>(bq, bk, bv,
                                                           dq, zq, dk, zk, dv, zv);
    // S = q . k^T * (dq*dk/16)
    mma_nt<<<dim3(NHW/128, NHW/128, NB), 256, mm_smem>>>(
        (const __half*)pq, (const __half*)pk, (float*)pS,
        NHW, NHW, NC, NC, NC, NHW, dq, dk, 0.0625f);
    softmax_kernel<<<NB*NHW, 256>>>(dw, zw);
    // h_out[n][c] = W . v^T * (dv*dw)
    mma_nt<<<dim3(NHW/128, NC/128, NB), 256, mm_smem>>>(
        (const __half*)pW, (const __half*)pv, (float*)pho,
        NHW, NC, NHW, NHW, NHW, NC, dv, dw, 1.0f);
    proj_kernel<<<dim3(NHW/64, NC/64, NB), 256>>>(wp, bp, x, out);
}

// round 16
// speedup vs baseline: 1.7385x; 1.0996x over previous
#include <cuda_runtime.h>
#include <cuda_fp16.h>
#include <cstdint>

#define NB 4
#define NC 256
#define NHW 4096
#define NG 32
#define CPG (NC/NG)

// ---------------- scratch (static device globals; no allocation) -------------
__device__ __half g_hhi[(size_t)NB*NHW*NC];  // groupnorm out hi, [b][n][c]
__device__ __half g_hlo[(size_t)NB*NHW*NC];  // groupnorm out lo residual
__device__ __half g_whi[4*NC*NC];            // wq/wk/wv/wproj hi
__device__ __half g_wlo[4*NC*NC];            // wq/wk/wv/wproj lo residual
__device__ __half g_q [(size_t)NB*NHW*NC];   // centered quant q, [b][n][c]
__device__ __half g_k [(size_t)NB*NHW*NC];   // centered quant k, [b][m][c]
__device__ __half g_v [(size_t)NB*NC*NHW];   // centered quant v, [b][c][m]
__device__ float  g_S [(size_t)NB*NHW*NHW];  // attn logits,     [b][n][m]
__device__ __half g_W [(size_t)NB*NHW*NHW];  // quant probs,     [b][n][m]
__device__ __half g_hoh[(size_t)NB*NHW*NC];  // attn out hi,     [b][n][c]
__device__ __half g_hol[(size_t)NB*NHW*NC];  // attn out lo residual

// ---------------- helpers ----------------------------------------------------
__device__ __forceinline__ void cp16(void* sm, const void* gm){
    unsigned sa = (unsigned)__cvta_generic_to_shared(sm);
    asm volatile("cp.async.cg.shared.global [%0], [%1], 16;\n" :: "r"(sa), "l"(gm));
}
__device__ __forceinline__ void cp_commit(){ asm volatile("cp.async.commit_group;\n"); }
template<int N> __device__ __forceinline__ void cp_wait(){
    asm volatile("cp.async.wait_group %0;\n" :: "n"(N));
}
__device__ __forceinline__ void mma16816(float* c, const unsigned* a, const unsigned* b){
    asm volatile(
        "mma.sync.aligned.m16n8k16.row.col.f32.f16.f16.f32 "
        "{%0,%1,%2,%3}, {%4,%5,%6,%7}, {%8,%9}, {%0,%1,%2,%3};\n"
        : "+f"(c[0]), "+f"(c[1]), "+f"(c[2]), "+f"(c[3])
        : "r"(a[0]), "r"(a[1]), "r"(a[2]), "r"(a[3]), "r"(b[0]), "r"(b[1]));
}
__device__ __forceinline__ void ldsm4(unsigned& r0, unsigned& r1, unsigned& r2, unsigned& r3,
                                      unsigned addr){
    asm volatile("ldmatrix.sync.aligned.m8n8.x4.shared.b16 {%0,%1,%2,%3}, [%4];\n"
                 : "=r"(r0), "=r"(r1), "=r"(r2), "=r"(r3) : "r"(addr));
}

// ---------------- 0. weight split prep (q,k,v,proj) ---------------------------
__global__ __launch_bounds__(256) void wsplit_kernel(const float* __restrict__ wq,
                                                     const float* __restrict__ wk,
                                                     const float* __restrict__ wv,
                                                     const float* __restrict__ wp){
    int i = blockIdx.x*256 + threadIdx.x;            // 0..65535
    const float* src[4] = {wq, wk, wv, wp};
    #pragma unroll
    for (int w = 0; w < 4; w++){
        float v = src[w][i];
        __half hi = __float2half_rn(v);
        __half lo = __float2half_rn(v - __half2float(hi));
        g_whi[w*NC*NC + i] = hi;
        g_wlo[w*NC*NC + i] = lo;
    }
}

// ---------------- 1. GroupNorm -> split fp16 hi/lo ----------------------------
__global__ __launch_bounds__(256) void gn_kernel(const float* __restrict__ x,
                                                 const float* __restrict__ sc,
                                                 const float* __restrict__ bi){
    int b = blockIdx.x / NG, g = blockIdx.x % NG;
    const float* xp = x + ((size_t)b*NC + (size_t)g*CPG)*NHW;
    const int NE = CPG*NHW;
    float s = 0.f, s2 = 0.f;
    for (int i = threadIdx.x; i < NE; i += 256){ float v = xp[i]; s += v; s2 += v*v; }
    __shared__ float r1[256], r2[256];
    r1[threadIdx.x] = s; r2[threadIdx.x] = s2; __syncthreads();
    for (int o = 128; o > 0; o >>= 1){
        if (threadIdx.x < o){ r1[threadIdx.x] += r1[threadIdx.x+o]; r2[threadIdx.x] += r2[threadIdx.x+o]; }
        __syncthreads();
    }
    float mean = r1[0] / NE;
    float var  = r2[0] / NE - mean*mean;
    float rstd = rsqrtf(var + 1e-6f);
    float scv[CPG], biv[CPG];
    #pragma unroll
    for (int c = 0; c < CPG; c++){ scv[c] = sc[g*CPG + c]*rstd; biv[c] = bi[g*CPG + c]; }
    for (int n = threadIdx.x; n < NHW; n += 256){
        __half hh[CPG], hl[CPG];
        #pragma unroll
        for (int c = 0; c < CPG; c++){
            float v = (xp[(size_t)c*NHW + n] - mean)*scv[c] + biv[c];
            hh[c] = __float2half_rn(v);
            hl[c] = __float2half_rn(v - __half2float(hh[c]));
        }
        size_t base = ((size_t)b*NHW + n)*NC + g*CPG;
        *(uint4*)&g_hhi[base] = *(uint4*)hh;
        *(uint4*)&g_hlo[base] = *(uint4*)hl;
    }
}

// ---------------- 2. QKV tensor-core GEMM (fp16-split) + quantize ------------
#define QK_LDS 40
#define QK_TILE (128*QK_LDS)
__global__ __launch_bounds__(256) void qkv_mma(
    const float* __restrict__ bq, const float* __restrict__ bk, const float* __restrict__ bv,
    const float* pdq, const float* pzq, const float* pdk, const float* pzk,
    const float* pdv, const float* pzv)
{
    extern __shared__ __align__(16) __half smem[];
    int b = blockIdx.z / 3, which = blockIdx.z % 3;
    const float *bias, *pd, *pz; __half* out;
    if (which == 0){ bias = bq; pd = pdq; pz = pzq; out = g_q; }
    else if (which == 1){ bias = bk; pd = pdk; pz = pzk; out = g_k; }
    else { bias = bv; pd = pdv; pz = pzv; out = g_v; }
    const __half* Ahi = g_hhi + (size_t)b*NHW*NC;
    const __half* Alo = g_hlo + (size_t)b*NHW*NC;
    const __half* Bhi = g_whi + which*NC*NC;
    const __half* Blo = g_wlo + which*NC*NC;

    int m0 = blockIdx.x*128, n0 = blockIdx.y*128;
    int tid = threadIdx.x, lane = tid & 31, warp = tid >> 5;
    int wm = warp >> 1, wn = warp & 1;
    int r = lane >> 2, cq = (lane & 3)*2;
    int lt = lane >> 3, l7 = lane & 7;
    unsigned aoff[2];
    #pragma unroll
    for (int i = 0; i < 2; i++)
        aoff[i] = ((wm*32 + i*16 + (lt&1)*8 + l7)*QK_LDS + (lt>>1)*8)*2;
    unsigned boff[4];
    #pragma unroll
    for (int jj = 0; jj < 4; jj++)
        boff[jj] = ((wn*64 + jj*16 + (lt>>1)*8 + l7)*QK_LDS + (lt&1)*8)*2;
    unsigned smBase = (unsigned)__cvta_generic_to_shared(smem);

    float acc[2][8][4];
    #pragma unroll
    for (int i = 0; i < 2; i++)
        #pragma unroll
        for (int j = 0; j < 8; j++)
            #pragma unroll
            for (int t = 0; t < 4; t++) acc[i][j][t] = 0.f;

    const __half* srcs[4] = {Ahi, Alo, Bhi, Blo};
    int KT = NC/32;
    auto prefetch = [&](int kt, int buf){
        int k0 = kt*32;
        #pragma unroll
        for (int t = 0; t < 4; t++){
            int rowbase = (t < 2) ? m0 : n0;
            __half* dst = smem + (buf*4 + t)*QK_TILE;
            #pragma unroll
            for (int it = 0; it < 2; ++it){
                int flat = tid + it*256;
                int row = flat >> 2, seg = flat & 3;
                cp16(dst + row*QK_LDS + seg*8,
                     srcs[t] + (size_t)(rowbase+row)*NC + k0 + seg*8);
            }
        }
        cp_commit();
    };

    prefetch(0, 0);
    for (int kt = 0; kt < KT; ++kt){
        int cur = kt & 1;
        if (kt + 1 < KT){ prefetch(kt+1, cur^1); cp_wait<1>(); }
        else            cp_wait<0>();
        __syncthreads();
        unsigned aHi = smBase + (cur*4 + 0)*QK_TILE*2;
        unsigned aLo = smBase + (cur*4 + 1)*QK_TILE*2;
        unsigned bHi = smBase + (cur*4 + 2)*QK_TILE*2;
        unsigned bLo = smBase + (cur*4 + 3)*QK_TILE*2;
        #pragma unroll
        for (int kk = 0; kk < 32; kk += 16){
            unsigned afh[2][4], afl[2][4], bfh[8][2], bfl[8][2];
            #pragma unroll
            for (int i = 0; i < 2; i++){
                ldsm4(afh[i][0], afh[i][1], afh[i][2], afh[i][3], aHi + aoff[i] + kk*2);
                ldsm4(afl[i][0], afl[i][1], afl[i][2], afl[i][3], aLo + aoff[i] + kk*2);
            }
            #pragma unroll
            for (int jj = 0; jj < 4; jj++){
                ldsm4(bfh[2*jj][0], bfh[2*jj][1], bfh[2*jj+1][0], bfh[2*jj+1][1],
                      bHi + boff[jj] + kk*2);
                ldsm4(bfl[2*jj][0], bfl[2*jj][1], bfl[2*jj+1][0], bfl[2*jj+1][1],
                      bLo + boff[jj] + kk*2);
            }
            #pragma unroll
            for (int i = 0; i < 2; i++)
                #pragma unroll
                for (int j = 0; j < 8; j++){
                    mma16816(acc[i][j], afh[i], bfh[j]);
                    mma16816(acc[i][j], afh[i], bfl[j]);
                    mma16816(acc[i][j], afl[i], bfh[j]);
                }
        }
        __syncthreads();
    }

    float delta = pd[0], zp = pz[0];
    float inv = 1.f/delta, qlo = -zp, qhi = 255.f - zp;
    #pragma unroll
    for (int i = 0; i < 2; i++)
        #pragma unroll
        for (int j = 0; j < 8; j++){
            int n  = m0 + wm*32 + i*16 + r;
            int o  = n0 + wn*64 + j*8 + cq;
            float b0 = bias[o], b1 = bias[o+1];
            float v00 = fminf(fmaxf(rintf((acc[i][j][0]+b0)*inv), qlo), qhi);
            float v01 = fminf(fmaxf(rintf((acc[i][j][1]+b1)*inv), qlo), qhi);
            float v10 = fminf(fmaxf(rintf((acc[i][j][2]+b0)*inv), qlo), qhi);
            float v11 = fminf(fmaxf(rintf((acc[i][j][3]+b1)*inv), qlo), qhi);
            if (which < 2){
                __half2 p0 = __halves2half2(__float2half_rn(v00), __float2half_rn(v01));
                __half2 p1 = __halves2half2(__float2half_rn(v10), __float2half_rn(v11));
                *(__half2*)&out[((size_t)b*NHW + n  )*NC + o] = p0;
                *(__half2*)&out[((size_t)b*NHW + n+8)*NC + o] = p1;
            } else {
                out[((size_t)b*NC + o  )*NHW + n  ] = __float2half_rn(v00);
                out[((size_t)b*NC + o+1)*NHW + n  ] = __float2half_rn(v01);
                out[((size_t)b*NC + o  )*NHW + n+8] = __float2half_rn(v10);
                out[((size_t)b*NC + o+1)*NHW + n+8] = __float2half_rn(v11);
            }
        }
}

// ---------------- 3/5. HMMA NT GEMM; fp32 out OR split-half out --------------
#define MM_STAGES 3
#define MM_LDS 40
#define MM_STAGE_HALFS (128*MM_LDS)
__global__ __launch_bounds__(256) void mma_nt(
    const __half* __restrict__ Ag, const __half* __restrict__ Bg, float* __restrict__ Cg,
    __half* __restrict__ Chi, __half* __restrict__ Clo,
    int M, int N, int K, int lda, int ldb, int ldc,
    const float* sa, const float* sb, float smul)
{
    extern __shared__ __align__(16) __half smem[];
    __half* As = smem;
    __half* Bs = smem + MM_STAGES*MM_STAGE_HALFS;
    int bz = blockIdx.z;
    const __half* A  = Ag + (size_t)bz*M*lda;
    const __half* Bp = Bg + (size_t)bz*N*ldb;
    int m0 = blockIdx.x*128, n0 = blockIdx.y*128;
    int tid = threadIdx.x, lane = tid & 31, warp = tid >> 5;
    int wm = warp >> 1, wn = warp & 1;
    int r = lane >> 2, cq = (lane & 3)*2;
    int lt = lane >> 3, l7 = lane & 7;
    unsigned aoff[2];
    #pragma unroll
    for (int i = 0; i < 2; i++)
        aoff[i] = ((wm*32 + i*16 + (lt&1)*8 + l7)*MM_LDS + (lt>>1)*8)*2;
    unsigned boff[4];
    #pragma unroll
    for (int jj = 0; jj < 4; jj++)
        boff[jj] = ((wn*64 + jj*16 + (lt>>1)*8 + l7)*MM_LDS + (lt&1)*8)*2;
    unsigned asBase = (unsigned)__cvta_generic_to_shared(As);
    unsigned bsBase = (unsigned)__cvta_generic_to_shared(Bs);

    float acc[2][8][4];
    #pragma unroll
    for (int i = 0; i < 2; i++)
        #pragma unroll
        for (int j = 0; j < 8; j++)
            #pragma unroll
            for (int t = 0; t < 4; t++) acc[i][j][t] = 0.f;

    int KT = K/32;
    auto prefetch = [&](int kt, int buf){
        int k0 = kt*32;
        __half* Ab_ = As + buf*MM_STAGE_HALFS;
        __half* Bb_ = Bs + buf*MM_STAGE_HALFS;
        #pragma unroll
        for (int it = 0; it < 2; ++it){
            int flat = tid + it*256;
            int row = flat >> 2, seg = flat & 3;
            cp16(Ab_ + row*MM_LDS + seg*8, A  + (size_t)(m0+row)*lda + k0 + seg*8);
            cp16(Bb_ + row*MM_LDS + seg*8, Bp + (size_t)(n0+row)*ldb + k0 + seg*8);
        }
        cp_commit();
    };

    prefetch(0, 0);
    prefetch(1, 1);
    for (int kt = 0; kt < KT; ++kt){
        int cur = kt % MM_STAGES;
        cp_wait<1>();
        __syncthreads();
        if (kt + 2 < KT) prefetch(kt+2, (kt+2) % MM_STAGES);
        unsigned aS = asBase + cur*MM_STAGE_HALFS*2;
        unsigned bS = bsBase + cur*MM_STAGE_HALFS*2;
        #pragma unroll
        for (int kk = 0; kk < 32; kk += 16){
            unsigned af[2][4], bf[8][2];
            #pragma unroll
            for (int i = 0; i < 2; i++)
                ldsm4(af[i][0], af[i][1], af[i][2], af[i][3], aS + aoff[i] + kk*2);
            #pragma unroll
            for (int jj = 0; jj < 4; jj++)
                ldsm4(bf[2*jj][0], bf[2*jj][1], bf[2*jj+1][0], bf[2*jj+1][1],
                      bS + boff[jj] + kk*2);
            #pragma unroll
            for (int i = 0; i < 2; i++)
                #pragma unroll
                for (int j = 0; j < 8; j++) mma16816(acc[i][j], af[i], bf[j]);
        }
    }
    float scale = sa[0]*sb[0]*smul;
    if (Chi == nullptr){
        float* Cp = Cg + (size_t)bz*M*ldc;
        #pragma unroll
        for (int i = 0; i < 2; i++)
            #pragma unroll
            for (int j = 0; j < 8; j++){
                int row = m0 + wm*32 + i*16 + r;
                int col = n0 + wn*64 + j*8 + cq;
                float2 v0 = make_float2(acc[i][j][0]*scale, acc[i][j][1]*scale);
                float2 v1 = make_float2(acc[i][j][2]*scale, acc[i][j][3]*scale);
                *(float2*)(Cp + (size_t)row*ldc + col)     = v0;
                *(float2*)(Cp + (size_t)(row+8)*ldc + col) = v1;
            }
    } else {
        __half* Ch = Chi + (size_t)bz*M*ldc;
        __half* Cl = Clo + (size_t)bz*M*ldc;
        #pragma unroll
        for (int i = 0; i < 2; i++)
            #pragma unroll
            for (int j = 0; j < 8; j++){
                int row = m0 + wm*32 + i*16 + r;
                int col = n0 + wn*64 + j*8 + cq;
                #pragma unroll
                for (int t = 0; t < 4; t++){
                    float v = acc[i][j][t]*scale;
                    __half hi = __float2half_rn(v);
                    __half lo = __float2half_rn(v - __half2float(hi));
                    size_t idx = (size_t)(row + (t>>1)*8)*ldc + col + (t&1);
                    Ch[idx] = hi;
                    Cl[idx] = lo;
                }
            }
    }
}

// ---------------- 4. softmax + prob quantization (register-resident) ---------
__global__ __launch_bounds__(256) void softmax_kernel(const float* pdw, const float* pzw){
    size_t rowi = blockIdx.x;
    const float4* S4 = (const float4*)(g_S + rowi*NHW);
    __half*       Wp = g_W + rowi*NHW;
    int tid = threadIdx.x, lane = tid & 31, wid = tid >> 5;
    __shared__ float redm[8], reds[8];

    float4 v[4];
    #pragma unroll
    for (int i = 0; i < 4; i++) v[i] = S4[tid + 256*i];

    float mx = -1e30f;
    #pragma unroll
    for (int i = 0; i < 4; i++){
        mx = fmaxf(mx, fmaxf(fmaxf(v[i].x, v[i].y), fmaxf(v[i].z, v[i].w)));
    }
    #pragma unroll
    for (int o = 16; o > 0; o >>= 1) mx = fmaxf(mx, __shfl_xor_sync(0xffffffffu, mx, o));
    if (lane == 0) redm[wid] = mx;
    __syncthreads();
    mx = redm[0];
    #pragma unroll
    for (int w = 1; w < 8; w++) mx = fmaxf(mx, redm[w]);

    float sum = 0.f;
    #pragma unroll
    for (int i = 0; i < 4; i++){
        v[i].x = __expf(v[i].x - mx); sum += v[i].x;
        v[i].y = __expf(v[i].y - mx); sum += v[i].y;
        v[i].z = __expf(v[i].z - mx); sum += v[i].z;
        v[i].w = __expf(v[i].w - mx); sum += v[i].w;
    }
    #pragma unroll
    for (int o = 16; o > 0; o >>= 1) sum += __shfl_xor_sync(0xffffffffu, sum, o);
    if (lane == 0) reds[wid] = sum;
    __syncthreads();
    float total = reds[0];
    #pragma unroll
    for (int w = 1; w < 8; w++) total += reds[w];

    float dwv = pdw[0], zwv = pzw[0];
    float inv = 1.f/(total*dwv);
    float lo = -zwv, hi = 255.f - zwv;
    #pragma unroll
    for (int i = 0; i < 4; i++){
        __half h0 = __float2half_rn(fminf(fmaxf(rintf(v[i].x*inv), lo), hi));
        __half h1 = __float2half_rn(fminf(fmaxf(rintf(v[i].y*inv), lo), hi));
        __half h2 = __float2half_rn(fminf(fmaxf(rintf(v[i].z*inv), lo), hi));
        __half h3 = __float2half_rn(fminf(fmaxf(rintf(v[i].w*inv), lo), hi));
        __half2 p0 = __halves2half2(h0, h1);
        __half2 p1 = __halves2half2(h2, h3);
        uint2 pk;
        pk.x = *(unsigned*)&p0;
        pk.y = *(unsigned*)&p1;
        *(uint2*)(Wp + 4*tid + 1024*i) = pk;
    }
}

// ---------------- 6. proj via split HMMA + bias + residual --------------------
// out[b][o][n] = x[b][o][n] + bp[o] + sum_c wproj[o][c]*ho[b][n][c]
__global__ __launch_bounds__(256) void proj_mma(
    const float* __restrict__ bp, const float* __restrict__ x, float* __restrict__ out)
{
    extern __shared__ __align__(16) __half smem[];   // [2][4][128][QK_LDS]
    int b = blockIdx.z;
    const __half* Ahi = g_whi + 3*NC*NC;             // wproj [o][c]
    const __half* Alo = g_wlo + 3*NC*NC;
    const __half* Bhi = g_hoh + (size_t)b*NHW*NC;    // ho [n][c]
    const __half* Blo = g_hol + (size_t)b*NHW*NC;

    int m0 = blockIdx.x*128, n0 = blockIdx.y*128;    // m0: o-dim, n0: n-dim
    int tid = threadIdx.x, lane = tid & 31, warp = tid >> 5;
    int wm = warp >> 1, wn = warp & 1;
    int r = lane >> 2, cq = (lane & 3)*2;
    int lt = lane >> 3, l7 = lane & 7;
    unsigned aoff[2];
    #pragma unroll
    for (int i = 0; i < 2; i++)
        aoff[i] = ((wm*32 + i*16 + (lt&1)*8 + l7)*QK_LDS + (lt>>1)*8)*2;
    unsigned boff[4];
    #pragma unroll
    for (int jj = 0; jj < 4; jj++)
        boff[jj] = ((wn*64 + jj*16 + (lt>>1)*8 + l7)*QK_LDS + (lt&1)*8)*2;
    unsigned smBase = (unsigned)__cvta_generic_to_shared(smem);

    float acc[2][8][4];
    #pragma unroll
    for (int i = 0; i < 2; i++)
        #pragma unroll
        for (int j = 0; j < 8; j++)
            #pragma unroll
            for (int t = 0; t < 4; t++) acc[i][j][t] = 0.f;

    const __half* srcs[4] = {Ahi, Alo, Bhi, Blo};
    int KT = NC/32;
    auto prefetch = [&](int kt, int buf){
        int k0 = kt*32;
        #pragma unroll
        for (int t = 0; t < 4; t++){
            int rowbase = (t < 2) ? m0 : n0;
            __half* dst = smem + (buf*4 + t)*QK_TILE;
            #pragma unroll
            for (int it = 0; it < 2; ++it){
                int flat = tid + it*256;
                int row = flat >> 2, seg = flat & 3;
                cp16(dst + row*QK_LDS + seg*8,
                     srcs[t] + (size_t)(rowbase+row)*NC + k0 + seg*8);
            }
        }
        cp_commit();
    };

    prefetch(0, 0);
    for (int kt = 0; kt < KT; ++kt){
        int cur = kt & 1;
        if (kt + 1 < KT){ prefetch(kt+1, cur^1); cp_wait<1>(); }
        else            cp_wait<0>();
        __syncthreads();
        unsigned aHi = smBase + (cur*4 + 0)*QK_TILE*2;
        unsigned aLo = smBase + (cur*4 + 1)*QK_TILE*2;
        unsigned bHi = smBase + (cur*4 + 2)*QK_TILE*2;
        unsigned bLo = smBase + (cur*4 + 3)*QK_TILE*2;
        #pragma unroll
        for (int kk = 0; kk < 32; kk += 16){
            unsigned afh[2][4], afl[2][4], bfh[8][2], bfl[8][2];
            #pragma unroll
            for (int i = 0; i < 2; i++){
                ldsm4(afh[i][0], afh[i][1], afh[i][2], afh[i][3], aHi + aoff[i] + kk*2);
                ldsm4(afl[i][0], afl[i][1], afl[i][2], afl[i][3], aLo + aoff[i] + kk*2);
            }
            #pragma unroll
            for (int jj = 0; jj < 4; jj++){
                ldsm4(bfh[2*jj][0], bfh[2*jj][1], bfh[2*jj+1][0], bfh[2*jj+1][1],
                      bHi + boff[jj] + kk*2);
                ldsm4(bfl[2*jj][0], bfl[2*jj][1], bfl[2*jj+1][0], bfl[2*jj+1][1],
                      bLo + boff[jj] + kk*2);
            }
            #pragma unroll
            for (int i = 0; i < 2; i++)
                #pragma unroll
                for (int j = 0; j < 8; j++){
                    mma16816(acc[i][j], afh[i], bfh[j]);
                    mma16816(acc[i][j], afh[i], bfl[j]);
                    mma16816(acc[i][j], afl[i], bfh[j]);
                }
        }
        __syncthreads();
    }

    #pragma unroll
    for (int i = 0; i < 2; i++)
        #pragma unroll
        for (int j = 0; j < 8; j++){
            int o   = m0 + wm*32 + i*16 + r;
            int col = n0 + wn*64 + j*8 + cq;
            size_t i0 = ((size_t)b*NC + o    )*NHW + col;
            size_t i1 = ((size_t)b*NC + o + 8)*NHW + col;
            float2 x0 = *(const float2*)(x + i0);
            float2 x1 = *(const float2*)(x + i1);
            float bp0 = bp[o], bp1 = bp[o+8];
            float2 v0 = make_float2(x0.x + bp0 + acc[i][j][0], x0.y + bp0 + acc[i][j][1]);
            float2 v1 = make_float2(x1.x + bp1 + acc[i][j][2], x1.y + bp1 + acc[i][j][3]);
            *(float2*)(out + i0) = v0;
            *(float2*)(out + i1) = v1;
        }
}

// ---------------- launch ------------------------------------------------------
extern "C" void kernel_launch(void* const* d_in, const int* in_sizes, int n_in,
                              void* d_out, int out_size){
    const float* x   = (const float*)d_in[0];
    const float* gsc = (const float*)d_in[1];
    const float* gbi = (const float*)d_in[2];
    const float* wq  = (const float*)d_in[3];  const float* bq = (const float*)d_in[4];
    const float* wk  = (const float*)d_in[5];  const float* bk = (const float*)d_in[6];
    const float* wv  = (const float*)d_in[7];  const float* bv = (const float*)d_in[8];
    const float* wp  = (const float*)d_in[9];  const float* bp = (const float*)d_in[10];
    const float* dq  = (const float*)d_in[11]; const float* zq = (const float*)d_in[12];
    const float* dk  = (const float*)d_in[13]; const float* zk = (const float*)d_in[14];
    const float* dv  = (const float*)d_in[15]; const float* zv = (const float*)d_in[16];
    const float* dw  = (const float*)d_in[17]; const float* zw = (const float*)d_in[18];
    float* out = (float*)d_out;

    void *pq, *pk, *pv, *pS, *pW, *phh, *phl;
    cudaGetSymbolAddress(&pq,  g_q);
    cudaGetSymbolAddress(&pk,  g_k);
    cudaGetSymbolAddress(&pv,  g_v);
    cudaGetSymbolAddress(&pS,  g_S);
    cudaGetSymbolAddress(&pW,  g_W);
    cudaGetSymbolAddress(&phh, g_hoh);
    cudaGetSymbolAddress(&phl, g_hol);

    const int mm_smem = MM_STAGES*MM_STAGE_HALFS*2*2;   // 61440 B
    cudaFuncSetAttribute(mma_nt, cudaFuncAttributeMaxDynamicSharedMemorySize, mm_smem);
    const int qk_smem = 2*4*QK_TILE*2;                  // 81920 B
    cudaFuncSetAttribute(qkv_mma, cudaFuncAttributeMaxDynamicSharedMemorySize, qk_smem);
    cudaFuncSetAttribute(proj_mma, cudaFuncAttributeMaxDynamicSharedMemorySize, qk_smem);

    wsplit_kernel<<<NC*NC/256, 256>>>(wq, wk, wv, wp);
    gn_kernel<<<NB*NG, 256>>>(x, gsc, gbi);
    qkv_mma<<<dim3(NHW/128, NC/128, NB*3), 256, qk_smem>>>(bq, bk, bv,
                                                           dq, zq, dk, zk, dv, zv);
    // S = q . k^T * (dq*dk/16)  -> fp32 g_S
    mma_nt<<<dim3(NHW/128, NHW/128, NB), 256, mm_smem>>>(
        (const __half*)pq, (const __half*)pk, (float*)pS, nullptr, nullptr,
        NHW, NHW, NC, NC, NC, NHW, dq, dk, 0.0625f);
    softmax_kernel<<<NB*NHW, 256>>>(dw, zw);
    // ho[n][c] = W . v^T * (dv*dw) -> split halves g_hoh/g_hol
    mma_nt<<<dim3(NHW/128, NC/128, NB), 256, mm_smem>>>(
        (const __half*)pW, (const __half*)pv, nullptr,
        (__half*)phh, (__half*)phl,
        NHW, NC, NHW, NHW, NHW, NC, dv, dw, 1.0f);
    // out = x + wproj . ho + bp
    proj_mma<<<dim3(NC/128, NHW/128, NB), 256, qk_smem>>>(bp, x, out);
}